// round 10
// baseline (speedup 1.0000x reference)
#include <cuda_runtime.h>
#include <cuda_bf16.h>
#include <cstdint>

#define MTOT 16384
#define DIM  512
#define NBATCH 128
#define SEQ 1024
#define DH 64

// Scratch (device globals = allocation-guard safe)
__device__ __align__(16) __nv_bfloat16 g_ah[MTOT * DIM];    // x split hi, later O split hi
__device__ __align__(16) __nv_bfloat16 g_al[MTOT * DIM];    // x split lo, later O split lo
__device__ __align__(16) __nv_bfloat16 g_wh[4][DIM * DIM];  // W^T hi
__device__ __align__(16) __nv_bfloat16 g_wl[4][DIM * DIM];  // W^T lo
__device__ __align__(16) __nv_bfloat16 g_qh[MTOT * DIM], g_ql[MTOT * DIM];
__device__ __align__(16) __nv_bfloat16 g_kh[MTOT * DIM], g_kl[MTOT * DIM];
__device__ __align__(16) __nv_bfloat16 g_vh[MTOT * DIM], g_vl[MTOT * DIM];
__device__ __align__(16) __nv_bfloat16 g_vth[MTOT * DIM], g_vtl[MTOT * DIM]; // V^T [n][dh][seq]

// ---------------------------------------------------------------------------
__device__ __forceinline__ uint32_t smem_u32(const void* p) {
    uint32_t a;
    asm("{ .reg .u64 t; cvta.to.shared.u64 t, %1; cvt.u32.u64 %0, t; }" : "=r"(a) : "l"(p));
    return a;
}

#define MMA_BF16(d, a, b0v, b1v)                                               \
    asm volatile("mma.sync.aligned.m16n8k16.row.col.f32.bf16.bf16.f32 "        \
                 "{%0,%1,%2,%3}, {%4,%5,%6,%7}, {%8,%9}, {%0,%1,%2,%3};"       \
                 : "+f"((d)[0]), "+f"((d)[1]), "+f"((d)[2]), "+f"((d)[3])      \
                 : "r"((a)[0]), "r"((a)[1]), "r"((a)[2]), "r"((a)[3]),         \
                   "r"(b0v), "r"(b1v))

#define LDSM_X4(r0, r1, r2, r3, addr)                                          \
    asm volatile("ldmatrix.sync.aligned.m8n8.x4.shared.b16 {%0,%1,%2,%3}, [%4];" \
                 : "=r"(r0), "=r"(r1), "=r"(r2), "=r"(r3) : "r"(addr))

__device__ __forceinline__ void cp16(uint32_t dst, const void* src) {
    asm volatile("cp.async.cg.shared.global [%0], [%1], 16;" :: "r"(dst), "l"(src) : "memory");
}
#define CP_COMMIT() asm volatile("cp.async.commit_group;" ::: "memory")
#define CP_WAIT(n)  asm volatile("cp.async.wait_group %0;" :: "n"(n) : "memory")

__device__ __forceinline__ uint32_t pack_bf16(float a, float b) {
    __nv_bfloat162 t(__float2bfloat16(a), __float2bfloat16(b));
    return *(uint32_t*)&t;
}

// ---------------------------------------------------------------------------
// Prep: weight transposes+splits (wq gets softmax scale folded), x split
// ---------------------------------------------------------------------------
__global__ void prep_w_kernel(const float* __restrict__ w0, const float* __restrict__ w1,
                              const float* __restrict__ w2, const float* __restrict__ w3) {
    const int wsel = blockIdx.y;
    const float* W = (wsel == 0) ? w0 : (wsel == 1) ? w1 : (wsel == 2) ? w2 : w3;
    int idx = blockIdx.x * 256 + threadIdx.x;      // idx = n*512 + k
    int k = idx & (DIM - 1);
    int n = idx >> 9;
    float f = W[k * DIM + n];
    if (wsel == 0) f *= 0.125f;
    __nv_bfloat16 h = __float2bfloat16(f);
    __nv_bfloat16 l = __float2bfloat16(f - __bfloat162float(h));
    g_wh[wsel][idx] = h;
    g_wl[wsel][idx] = l;
}

__global__ void split_x_kernel(const float* __restrict__ src) {
    int i = blockIdx.x * 256 + threadIdx.x;        // 4 floats per thread
    float4 v = ((const float4*)src)[i];
    float f[4] = {v.x, v.y, v.z, v.w};
    __nv_bfloat16 h[4], l[4];
#pragma unroll
    for (int j = 0; j < 4; j++) {
        h[j] = __float2bfloat16(f[j]);
        l[j] = __float2bfloat16(f[j] - __bfloat162float(h[j]));
    }
    ((__nv_bfloat162*)g_ah)[2 * i]     = __nv_bfloat162(h[0], h[1]);
    ((__nv_bfloat162*)g_ah)[2 * i + 1] = __nv_bfloat162(h[2], h[3]);
    ((__nv_bfloat162*)g_al)[2 * i]     = __nv_bfloat162(l[0], l[1]);
    ((__nv_bfloat162*)g_al)[2 * i + 1] = __nv_bfloat162(l[2], l[3]);
}

// ---------------------------------------------------------------------------
// V transpose: g_vh/g_vl [n][seq][dh] -> g_vth/g_vtl [n][dh][seq]
// ---------------------------------------------------------------------------
__global__ void __launch_bounds__(256) transpose_v_kernel()
{
    __shared__ uint32_t tile[64][65];
    const int n  = blockIdx.y;
    const int st = blockIdx.x;
    const int tid = threadIdx.x;
    {
        int s  = tid >> 2;
        int d0 = (tid & 3) * 16;
        const __nv_bfloat16* ph = g_vh + (size_t)n * 65536 + (st * 64 + s) * 64 + d0;
        const __nv_bfloat16* pl = g_vl + (size_t)n * 65536 + (st * 64 + s) * 64 + d0;
        uint4 h0 = *(const uint4*)(ph);
        uint4 h1 = *(const uint4*)(ph + 8);
        uint4 l0 = *(const uint4*)(pl);
        uint4 l1 = *(const uint4*)(pl + 8);
        const uint16_t* hs = (const uint16_t*)&h0;
        const uint16_t* ls = (const uint16_t*)&l0;
#pragma unroll
        for (int j = 0; j < 8; j++)
            tile[s][d0 + j] = (uint32_t)hs[j] | ((uint32_t)ls[j] << 16);
        const uint16_t* hs1 = (const uint16_t*)&h1;
        const uint16_t* ls1 = (const uint16_t*)&l1;
#pragma unroll
        for (int j = 0; j < 8; j++)
            tile[s][d0 + 8 + j] = (uint32_t)hs1[j] | ((uint32_t)ls1[j] << 16);
    }
    __syncthreads();
    {
        int d  = tid >> 2;
        int s0 = (tid & 3) * 16;
        uint16_t hb[16], lb[16];
#pragma unroll
        for (int j = 0; j < 16; j++) {
            uint32_t w = tile[s0 + j][d];
            hb[j] = (uint16_t)(w & 0xFFFF);
            lb[j] = (uint16_t)(w >> 16);
        }
        __nv_bfloat16* oh = g_vth + (size_t)n * 65536 + d * 1024 + st * 64 + s0;
        __nv_bfloat16* ol = g_vtl + (size_t)n * 65536 + d * 1024 + st * 64 + s0;
        *(uint4*)(oh)     = *(uint4*)&hb[0];
        *(uint4*)(oh + 8) = *(uint4*)&hb[8];
        *(uint4*)(ol)     = *(uint4*)&lb[0];
        *(uint4*)(ol + 8) = *(uint4*)&lb[8];
    }
}

// ---------------------------------------------------------------------------
// Tensor-core GEMM, bf16x3, ldmatrix loads. CTA tile 256x128, 512 threads
// (16 warps = 8m x 2n, warp tile 32x64), k-chunk 32, 2-stage cp.async.
// smem/stage: Ah 20480 | Al 20480 | Bh 10240 | Bl 10240 = 61440; x2 = 122880.
// ---------------------------------------------------------------------------
#define RS 40
#define GA_SZ (256 * RS * 2)           // 20480
#define GB_SZ (128 * RS * 2)           // 10240
#define GSTG  (2 * GA_SZ + 2 * GB_SZ)  // 61440
#define GSM_TOTAL (2 * GSTG)           // 122880

__global__ void __launch_bounds__(512, 1) gemm_mma_kernel(
    const float* __restrict__ bq, const float* __restrict__ bk,
    const float* __restrict__ bv, float* __restrict__ Cext, int dst_override)
{
    extern __shared__ char smem[];
    const uint32_t sb = smem_u32(smem);
    const int tid  = threadIdx.x;
    const int wid  = tid >> 5;         // 0..15
    const int lane = tid & 31;
    const int g    = lane >> 2;
    const int q    = lane & 3;
    const int lj   = lane >> 3;
    const int li   = lane & 7;
    const int wm   = wid >> 1;         // 0..7 -> m offset wm*32
    const int wn   = wid & 1;          // 0..1 -> n offset wn*64
    const int n0   = blockIdx.x * 128;
    const int m0   = blockIdx.y * 256;

    const int dst_sel = (dst_override < 0) ? -1 : (int)blockIdx.z;
    const int wsel    = (dst_override < 0) ? 3 : (int)blockIdx.z;
    const float* bias = (dst_override < 0) ? bq
                        : (dst_sel == 0) ? bq : (dst_sel == 1) ? bk : bv;
    const float bscale = (dst_sel == 0) ? 0.125f : 1.0f;

    const __nv_bfloat16* __restrict__ Bh = g_wh[wsel];
    const __nv_bfloat16* __restrict__ Bl = g_wl[wsel];

    float acc[2][8][4];
#pragma unroll
    for (int mf = 0; mf < 2; mf++)
#pragma unroll
        for (int nf = 0; nf < 8; nf++)
#pragma unroll
            for (int r = 0; r < 4; r++) acc[mf][nf][r] = 0.f;

    auto stage = [&](int buf, int kc) {
        uint32_t base = sb + buf * GSTG;
        // A hi/lo: 256 rows x 4 granules = 1024 -> 2 iters of 512 threads
#pragma unroll
        for (int it = 0; it < 2; it++) {
            int gdx = tid + 512 * it;
            int r   = gdx >> 2;
            int qq  = gdx & 3;
            uint32_t doff = (uint32_t)(r * RS * 2 + qq * 16);
            size_t aoff = (size_t)(m0 + r) * DIM + kc + qq * 8;
            cp16(base + doff,         g_ah + aoff);
            cp16(base + GA_SZ + doff, g_al + aoff);
        }
        // B hi/lo: 128 rows x 4 granules = 512 -> 1 iter
        {
            int r  = tid >> 2;
            int qq = tid & 3;
            uint32_t doff = (uint32_t)(r * RS * 2 + qq * 16);
            size_t boff = (size_t)(n0 + r) * DIM + kc + qq * 8;
            cp16(base + 2 * GA_SZ + doff,         Bh + boff);
            cp16(base + 2 * GA_SZ + GB_SZ + doff, Bl + boff);
        }
    };

    stage(0, 0);
    CP_COMMIT();

    const int a_row_lane = ((lj & 1) << 3) + li;
    const int a_col_lane = (lj >> 1) << 3;
    const int b_row_lane = ((lj >> 1) << 3) + li;
    const int b_col_lane = (lj & 1) << 3;

    for (int kt = 0; kt < 16; kt++) {
        if (kt < 15) {
            stage((kt + 1) & 1, (kt + 1) * 32);
            CP_COMMIT();
            CP_WAIT(1);
        } else {
            CP_WAIT(0);
        }
        __syncthreads();

        const uint32_t base = sb + (kt & 1) * GSTG;
        const uint32_t bAh = base, bAl = base + GA_SZ;
        const uint32_t bBh = base + 2 * GA_SZ, bBl = base + 2 * GA_SZ + GB_SZ;

#pragma unroll
        for (int s = 0; s < 2; s++) {
            const int kb = s * 16;
            uint32_t ah[2][4], al[2][4];
#pragma unroll
            for (int mf = 0; mf < 2; mf++) {
                uint32_t ro = (uint32_t)((wm * 32 + mf * 16 + a_row_lane) * RS
                                         + kb + a_col_lane) * 2;
                LDSM_X4(ah[mf][0], ah[mf][1], ah[mf][2], ah[mf][3], bAh + ro);
                LDSM_X4(al[mf][0], al[mf][1], al[mf][2], al[mf][3], bAl + ro);
            }
#pragma unroll
            for (int nfp = 0; nfp < 4; nfp++) {
                uint32_t ro = (uint32_t)((wn * 64 + nfp * 16 + b_row_lane) * RS
                                         + kb + b_col_lane) * 2;
                uint32_t h0, h1, h2, h3, l0, l1, l2, l3;
                LDSM_X4(h0, h1, h2, h3, bBh + ro);
                LDSM_X4(l0, l1, l2, l3, bBl + ro);
#pragma unroll
                for (int mf = 0; mf < 2; mf++) {
                    MMA_BF16(acc[mf][2 * nfp],     ah[mf], h0, h1);
                    MMA_BF16(acc[mf][2 * nfp],     ah[mf], l0, l1);
                    MMA_BF16(acc[mf][2 * nfp],     al[mf], h0, h1);
                    MMA_BF16(acc[mf][2 * nfp + 1], ah[mf], h2, h3);
                    MMA_BF16(acc[mf][2 * nfp + 1], ah[mf], l2, l3);
                    MMA_BF16(acc[mf][2 * nfp + 1], al[mf], h2, h3);
                }
            }
        }
        __syncthreads();
    }

    __nv_bfloat16 *dsth = nullptr, *dstl = nullptr;
    if (dst_sel == 0) { dsth = g_qh; dstl = g_ql; }
    else if (dst_sel == 1) { dsth = g_kh; dstl = g_kl; }
    else if (dst_sel == 2) { dsth = g_vh; dstl = g_vl; }

#pragma unroll
    for (int mf = 0; mf < 2; mf++) {
        int row = m0 + wm * 32 + mf * 16 + g;
#pragma unroll
        for (int nf = 0; nf < 8; nf++) {
            int col = n0 + wn * 64 + nf * 8 + 2 * q;
            float2 bb = *(const float2*)(bias + col);
            bb.x *= bscale;  bb.y *= bscale;
            float o0 = acc[mf][nf][0] + bb.x, o1 = acc[mf][nf][1] + bb.y;
            float o2 = acc[mf][nf][2] + bb.x, o3 = acc[mf][nf][3] + bb.y;
            if (dst_sel < 0) {
                *(float2*)(Cext + (size_t)row * DIM + col)       = make_float2(o0, o1);
                *(float2*)(Cext + (size_t)(row + 8) * DIM + col) = make_float2(o2, o3);
            } else {
                float h0 = __bfloat162float(__float2bfloat16(o0));
                float h1 = __bfloat162float(__float2bfloat16(o1));
                float h2 = __bfloat162float(__float2bfloat16(o2));
                float h3 = __bfloat162float(__float2bfloat16(o3));
                *(uint32_t*)(dsth + (size_t)row * DIM + col)       = pack_bf16(h0, h1);
                *(uint32_t*)(dsth + (size_t)(row + 8) * DIM + col) = pack_bf16(h2, h3);
                *(uint32_t*)(dstl + (size_t)row * DIM + col)       = pack_bf16(o0 - h0, o1 - h1);
                *(uint32_t*)(dstl + (size_t)(row + 8) * DIM + col) = pack_bf16(o2 - h2, o3 - h3);
            }
        }
    }
}

// ---------------------------------------------------------------------------
// Flash attention via mma.sync, bf16x3 both matmuls, ldmatrix loads (at ~90%
// of register-mma roofline; unchanged).
// ---------------------------------------------------------------------------
#define AKS 72
#define ATILE (64 * AKS * 2)              // 9216 B per array
#define ASTG  (4 * ATILE)                 // 36864 per stage
#define ASM_TOTAL (2 * ASTG)              // 73728

__global__ void __launch_bounds__(256, 2) attn_mma_kernel()
{
    extern __shared__ char smem[];
    const uint32_t sb = smem_u32(smem);
    const int tid  = threadIdx.x;
    const int wid  = tid >> 5;
    const int lane = tid & 31;
    const int g    = lane >> 2;
    const int q    = lane & 3;
    const int lj   = lane >> 3;
    const int li   = lane & 7;
    const int n    = blockIdx.y;
    const int qt   = blockIdx.x;

    const size_t nb = (size_t)n * 65536;
    const __nv_bfloat16* qhp = g_qh + nb + (qt * 128) * 64;
    const __nv_bfloat16* qlp = g_ql + nb + (qt * 128) * 64;

    uint32_t qah[4][4], qal[4][4];
    const int r0 = wid * 16 + g, r1 = r0 + 8;
#pragma unroll
    for (int ks = 0; ks < 4; ks++) {
        int c = ks * 16 + 2 * q;
        qah[ks][0] = *(const uint32_t*)(qhp + r0 * 64 + c);
        qah[ks][1] = *(const uint32_t*)(qhp + r1 * 64 + c);
        qah[ks][2] = *(const uint32_t*)(qhp + r0 * 64 + c + 8);
        qah[ks][3] = *(const uint32_t*)(qhp + r1 * 64 + c + 8);
        qal[ks][0] = *(const uint32_t*)(qlp + r0 * 64 + c);
        qal[ks][1] = *(const uint32_t*)(qlp + r1 * 64 + c);
        qal[ks][2] = *(const uint32_t*)(qlp + r0 * 64 + c + 8);
        qal[ks][3] = *(const uint32_t*)(qlp + r1 * 64 + c + 8);
    }

    float oacc[8][4];
#pragma unroll
    for (int i = 0; i < 8; i++)
#pragma unroll
        for (int j = 0; j < 4; j++) oacc[i][j] = 0.f;
    float m0 = -1e30f, m1 = -1e30f, l0 = 0.f, l1 = 0.f;

    auto stage = [&](int buf, int kt) {
        uint32_t base = sb + buf * ASTG;
#pragma unroll
        for (int it = 0; it < 2; it++) {
            int gdx = tid + 256 * it;
            int r  = gdx >> 3;
            int qq = gdx & 7;
            uint32_t doff = (uint32_t)(r * (AKS * 2) + qq * 16);
            size_t koff = nb + (size_t)(kt * 64 + r) * 64 + qq * 8;
            size_t voff = nb + (size_t)r * 1024 + kt * 64 + qq * 8;
            cp16(base + doff,             g_kh + koff);
            cp16(base + ATILE + doff,     g_kl + koff);
            cp16(base + 2 * ATILE + doff, g_vth + voff);
            cp16(base + 3 * ATILE + doff, g_vtl + voff);
        }
    };

    stage(0, 0);
    CP_COMMIT();

    const int b_row_lane = ((lj >> 1) << 3) + li;
    const int b_col_lane = (lj & 1) << 3;

    for (int kt = 0; kt < 16; kt++) {
        if (kt < 15) {
            stage((kt + 1) & 1, kt + 1);
            CP_COMMIT();
            CP_WAIT(1);
        } else {
            CP_WAIT(0);
        }
        __syncthreads();

        const uint32_t base = sb + (kt & 1) * ASTG;
        const uint32_t bKh = base, bKl = base + ATILE;
        const uint32_t bVh = base + 2 * ATILE, bVl = base + 3 * ATILE;

        float s[8][4];
#pragma unroll
        for (int nf = 0; nf < 8; nf++)
#pragma unroll
            for (int j = 0; j < 4; j++) s[nf][j] = 0.f;

#pragma unroll
        for (int ks = 0; ks < 4; ks++) {
#pragma unroll
            for (int nfp = 0; nfp < 4; nfp++) {
                uint32_t ro = (uint32_t)((nfp * 16 + b_row_lane) * AKS
                                         + ks * 16 + b_col_lane) * 2;
                uint32_t h0, h1, h2, h3, l0r, l1r, l2r, l3r;
                LDSM_X4(h0, h1, h2, h3, bKh + ro);
                LDSM_X4(l0r, l1r, l2r, l3r, bKl + ro);
                MMA_BF16(s[2 * nfp],     qah[ks], h0, h1);
                MMA_BF16(s[2 * nfp],     qah[ks], l0r, l1r);
                MMA_BF16(s[2 * nfp],     qal[ks], h0, h1);
                MMA_BF16(s[2 * nfp + 1], qah[ks], h2, h3);
                MMA_BF16(s[2 * nfp + 1], qah[ks], l2r, l3r);
                MMA_BF16(s[2 * nfp + 1], qal[ks], h2, h3);
            }
        }

        float mn0 = m0, mn1 = m1;
#pragma unroll
        for (int nf = 0; nf < 8; nf++) {
            mn0 = fmaxf(mn0, fmaxf(s[nf][0], s[nf][1]));
            mn1 = fmaxf(mn1, fmaxf(s[nf][2], s[nf][3]));
        }
#pragma unroll
        for (int off = 1; off <= 2; off <<= 1) {
            mn0 = fmaxf(mn0, __shfl_xor_sync(0xffffffffu, mn0, off));
            mn1 = fmaxf(mn1, __shfl_xor_sync(0xffffffffu, mn1, off));
        }
        float f0 = __expf(m0 - mn0), f1 = __expf(m1 - mn1);
        m0 = mn0;  m1 = mn1;

        uint32_t ph[8], ph2[8], pl[8], pl2[8];
        float ls0 = 0.f, ls1 = 0.f;
#pragma unroll
        for (int nf = 0; nf < 8; nf++) {
            float p0 = __expf(s[nf][0] - m0);
            float p1 = __expf(s[nf][1] - m0);
            float p2 = __expf(s[nf][2] - m1);
            float p3 = __expf(s[nf][3] - m1);
            ls0 += p0 + p1;  ls1 += p2 + p3;
            float h0 = __bfloat162float(__float2bfloat16(p0));
            float h1 = __bfloat162float(__float2bfloat16(p1));
            float h2 = __bfloat162float(__float2bfloat16(p2));
            float h3 = __bfloat162float(__float2bfloat16(p3));
            ph[nf]  = pack_bf16(h0, h1);
            ph2[nf] = pack_bf16(h2, h3);
            pl[nf]  = pack_bf16(p0 - h0, p1 - h1);
            pl2[nf] = pack_bf16(p2 - h2, p3 - h3);
        }
#pragma unroll
        for (int off = 1; off <= 2; off <<= 1) {
            ls0 += __shfl_xor_sync(0xffffffffu, ls0, off);
            ls1 += __shfl_xor_sync(0xffffffffu, ls1, off);
        }
        l0 = l0 * f0 + ls0;
        l1 = l1 * f1 + ls1;
#pragma unroll
        for (int dhf = 0; dhf < 8; dhf++) {
            oacc[dhf][0] *= f0;  oacc[dhf][1] *= f0;
            oacc[dhf][2] *= f1;  oacc[dhf][3] *= f1;
        }

#pragma unroll
        for (int ks = 0; ks < 4; ks++) {
            uint32_t a_h[4] = {ph[2 * ks], ph2[2 * ks], ph[2 * ks + 1], ph2[2 * ks + 1]};
            uint32_t a_l[4] = {pl[2 * ks], pl2[2 * ks], pl[2 * ks + 1], pl2[2 * ks + 1]};
#pragma unroll
            for (int dhp = 0; dhp < 4; dhp++) {
                uint32_t ro = (uint32_t)((dhp * 16 + b_row_lane) * AKS
                                         + ks * 16 + b_col_lane) * 2;
                uint32_t h0, h1, h2, h3, l0r, l1r, l2r, l3r;
                LDSM_X4(h0, h1, h2, h3, bVh + ro);
                LDSM_X4(l0r, l1r, l2r, l3r, bVl + ro);
                MMA_BF16(oacc[2 * dhp],     a_h, h0, h1);
                MMA_BF16(oacc[2 * dhp],     a_h, l0r, l1r);
                MMA_BF16(oacc[2 * dhp],     a_l, h0, h1);
                MMA_BF16(oacc[2 * dhp + 1], a_h, h2, h3);
                MMA_BF16(oacc[2 * dhp + 1], a_h, l2r, l3r);
                MMA_BF16(oacc[2 * dhp + 1], a_l, h2, h3);
            }
        }
        __syncthreads();
    }

    float inv0 = 1.0f / l0, inv1 = 1.0f / l1;
    const size_t ob0 = nb + (size_t)(qt * 128 + r0) * 64;
    const size_t ob1 = nb + (size_t)(qt * 128 + r1) * 64;
#pragma unroll
    for (int dhf = 0; dhf < 8; dhf++) {
        int col = dhf * 8 + 2 * q;
        float o0 = oacc[dhf][0] * inv0, o1 = oacc[dhf][1] * inv0;
        float o2 = oacc[dhf][2] * inv1, o3 = oacc[dhf][3] * inv1;
        float h0 = __bfloat162float(__float2bfloat16(o0));
        float h1 = __bfloat162float(__float2bfloat16(o1));
        float h2 = __bfloat162float(__float2bfloat16(o2));
        float h3 = __bfloat162float(__float2bfloat16(o3));
        *(uint32_t*)(g_ah + ob0 + col) = pack_bf16(h0, h1);
        *(uint32_t*)(g_ah + ob1 + col) = pack_bf16(h2, h3);
        *(uint32_t*)(g_al + ob0 + col) = pack_bf16(o0 - h0, o1 - h1);
        *(uint32_t*)(g_al + ob1 + col) = pack_bf16(o2 - h2, o3 - h3);
    }
}

// ---------------------------------------------------------------------------
extern "C" void kernel_launch(void* const* d_in, const int* in_sizes, int n_in,
                              void* d_out, int out_size)
{
    const float* x  = (const float*)d_in[0];
    const float* wq = (const float*)d_in[1];
    const float* bq = (const float*)d_in[2];
    const float* wk = (const float*)d_in[3];
    const float* bk = (const float*)d_in[4];
    const float* wv = (const float*)d_in[5];
    const float* bv = (const float*)d_in[6];
    const float* wo = (const float*)d_in[7];
    const float* bo = (const float*)d_in[8];
    float* out = (float*)d_out;

    static bool attr_set = false;
    if (!attr_set) {
        cudaFuncSetAttribute(gemm_mma_kernel,
                             cudaFuncAttributeMaxDynamicSharedMemorySize, GSM_TOTAL);
        cudaFuncSetAttribute(attn_mma_kernel,
                             cudaFuncAttributeMaxDynamicSharedMemorySize, ASM_TOTAL);
        attr_set = true;
    }

    prep_w_kernel<<<dim3(1024, 4), 256>>>(wq, wk, wv, wo);
    split_x_kernel<<<8192, 256>>>(x);

    // Fused Q/K/V projections: 256-row m-tiles, blockIdx.z selects weight+dst
    gemm_mma_kernel<<<dim3(4, 64, 3), 512, GSM_TOTAL>>>(bq, bk, bv, nullptr, 0);

    transpose_v_kernel<<<dim3(16, NBATCH), 256>>>();              // Vt hi/lo

    attn_mma_kernel<<<dim3(8, NBATCH), 256, ASM_TOTAL>>>();       // O -> g_ah/g_al

    // Output projection (wsel=3, fp32 out)
    gemm_mma_kernel<<<dim3(4, 64, 1), 512, GSM_TOTAL>>>(bo, nullptr, nullptr, out, -1);
}

// round 11
// speedup vs baseline: 1.6589x; 1.6589x over previous
#include <cuda_runtime.h>
#include <cuda_bf16.h>
#include <cstdint>

#define MTOT 16384
#define DIM  512
#define NBATCH 128
#define SEQ 1024
#define DH 64

// Scratch (device globals = allocation-guard safe)
__device__ __align__(16) __nv_bfloat16 g_ah[MTOT * DIM];    // x split hi, later O split hi
__device__ __align__(16) __nv_bfloat16 g_al[MTOT * DIM];    // x split lo, later O split lo
__device__ __align__(16) __nv_bfloat16 g_wh[4][DIM * DIM];  // W^T hi
__device__ __align__(16) __nv_bfloat16 g_wl[4][DIM * DIM];  // W^T lo
__device__ __align__(16) __nv_bfloat16 g_qh[MTOT * DIM], g_ql[MTOT * DIM];
__device__ __align__(16) __nv_bfloat16 g_kh[MTOT * DIM], g_kl[MTOT * DIM];
__device__ __align__(16) __nv_bfloat16 g_vh[MTOT * DIM], g_vl[MTOT * DIM];

// ---------------------------------------------------------------------------
__device__ __forceinline__ uint32_t smem_u32(const void* p) {
    uint32_t a;
    asm("{ .reg .u64 t; cvta.to.shared.u64 t, %1; cvt.u32.u64 %0, t; }" : "=r"(a) : "l"(p));
    return a;
}

#define MMA_BF16(d, a, b0v, b1v)                                               \
    asm volatile("mma.sync.aligned.m16n8k16.row.col.f32.bf16.bf16.f32 "        \
                 "{%0,%1,%2,%3}, {%4,%5,%6,%7}, {%8,%9}, {%0,%1,%2,%3};"       \
                 : "+f"((d)[0]), "+f"((d)[1]), "+f"((d)[2]), "+f"((d)[3])      \
                 : "r"((a)[0]), "r"((a)[1]), "r"((a)[2]), "r"((a)[3]),         \
                   "r"(b0v), "r"(b1v))

#define LDSM_X4(r0, r1, r2, r3, addr)                                          \
    asm volatile("ldmatrix.sync.aligned.m8n8.x4.shared.b16 {%0,%1,%2,%3}, [%4];" \
                 : "=r"(r0), "=r"(r1), "=r"(r2), "=r"(r3) : "r"(addr))

// Transposing variant: canonical path for row-major (K x N) B operands.
#define LDSM_X4_T(r0, r1, r2, r3, addr)                                        \
    asm volatile("ldmatrix.sync.aligned.m8n8.x4.trans.shared.b16 {%0,%1,%2,%3}, [%4];" \
                 : "=r"(r0), "=r"(r1), "=r"(r2), "=r"(r3) : "r"(addr))

__device__ __forceinline__ void cp16(uint32_t dst, const void* src) {
    asm volatile("cp.async.cg.shared.global [%0], [%1], 16;" :: "r"(dst), "l"(src) : "memory");
}
#define CP_COMMIT() asm volatile("cp.async.commit_group;" ::: "memory")
#define CP_WAIT(n)  asm volatile("cp.async.wait_group %0;" :: "n"(n) : "memory")

__device__ __forceinline__ uint32_t pack_bf16(float a, float b) {
    __nv_bfloat162 t(__float2bfloat16(a), __float2bfloat16(b));
    return *(uint32_t*)&t;
}

// ---------------------------------------------------------------------------
// Prep: weight transposes+splits (wq gets softmax scale folded), x split
// ---------------------------------------------------------------------------
__global__ void prep_w_kernel(const float* __restrict__ w0, const float* __restrict__ w1,
                              const float* __restrict__ w2, const float* __restrict__ w3) {
    const int wsel = blockIdx.y;
    const float* W = (wsel == 0) ? w0 : (wsel == 1) ? w1 : (wsel == 2) ? w2 : w3;
    int idx = blockIdx.x * 256 + threadIdx.x;      // idx = n*512 + k
    int k = idx & (DIM - 1);
    int n = idx >> 9;
    float f = W[k * DIM + n];
    if (wsel == 0) f *= 0.125f;
    __nv_bfloat16 h = __float2bfloat16(f);
    __nv_bfloat16 l = __float2bfloat16(f - __bfloat162float(h));
    g_wh[wsel][idx] = h;
    g_wl[wsel][idx] = l;
}

__global__ void split_x_kernel(const float* __restrict__ src) {
    int i = blockIdx.x * 256 + threadIdx.x;        // 4 floats per thread
    float4 v = ((const float4*)src)[i];
    float f[4] = {v.x, v.y, v.z, v.w};
    __nv_bfloat16 h[4], l[4];
#pragma unroll
    for (int j = 0; j < 4; j++) {
        h[j] = __float2bfloat16(f[j]);
        l[j] = __float2bfloat16(f[j] - __bfloat162float(h[j]));
    }
    ((__nv_bfloat162*)g_ah)[2 * i]     = __nv_bfloat162(h[0], h[1]);
    ((__nv_bfloat162*)g_ah)[2 * i + 1] = __nv_bfloat162(h[2], h[3]);
    ((__nv_bfloat162*)g_al)[2 * i]     = __nv_bfloat162(l[0], l[1]);
    ((__nv_bfloat162*)g_al)[2 * i + 1] = __nv_bfloat162(l[2], l[3]);
}

// ---------------------------------------------------------------------------
// Tensor-core GEMM, bf16x3, ldmatrix loads. ROUND-9 CONFIG (known good):
// CTA 128x128, 256 threads, 2 CTA/SM (co-resident CTAs hide pipeline latency).
// ---------------------------------------------------------------------------
#define RS 40
#define TILE_B (128 * RS * 2)
#define GSM_TOTAL (2 * 4 * TILE_B)     // 81920

__global__ void __launch_bounds__(256, 2) gemm_mma_kernel(
    const float* __restrict__ bq, const float* __restrict__ bk,
    const float* __restrict__ bv, float* __restrict__ Cext, int dst_override)
{
    extern __shared__ char smem[];
    const uint32_t sb = smem_u32(smem);
    const int tid  = threadIdx.x;
    const int wid  = tid >> 5;
    const int lane = tid & 31;
    const int g    = lane >> 2;
    const int q    = lane & 3;
    const int lj   = lane >> 3;
    const int li   = lane & 7;
    const int wm   = wid >> 1;
    const int wn   = wid & 1;
    const int n0   = blockIdx.x * 128;
    const int m0   = blockIdx.y * 128;

    const int dst_sel = (dst_override < 0) ? -1 : (int)blockIdx.z;
    const int wsel    = (dst_override < 0) ? 3 : (int)blockIdx.z;
    const float* bias = (dst_override < 0) ? bq
                        : (dst_sel == 0) ? bq : (dst_sel == 1) ? bk : bv;
    const float bscale = (dst_sel == 0) ? 0.125f : 1.0f;

    const __nv_bfloat16* __restrict__ Bh = g_wh[wsel];
    const __nv_bfloat16* __restrict__ Bl = g_wl[wsel];

    float acc[2][8][4];
#pragma unroll
    for (int mf = 0; mf < 2; mf++)
#pragma unroll
        for (int nf = 0; nf < 8; nf++)
#pragma unroll
            for (int r = 0; r < 4; r++) acc[mf][nf][r] = 0.f;

    auto stage = [&](int buf, int kc) {
        uint32_t base = sb + buf * 4 * TILE_B;
#pragma unroll
        for (int it = 0; it < 2; it++) {
            int gdx = tid + 256 * it;
            int r   = gdx >> 2;
            int qq  = gdx & 3;
            uint32_t doff = (uint32_t)(r * RS * 2 + qq * 16);
            size_t aoff = (size_t)(m0 + r) * DIM + kc + qq * 8;
            size_t boff = (size_t)(n0 + r) * DIM + kc + qq * 8;
            cp16(base + doff,              g_ah + aoff);
            cp16(base + TILE_B + doff,     g_al + aoff);
            cp16(base + 2 * TILE_B + doff, Bh + boff);
            cp16(base + 3 * TILE_B + doff, Bl + boff);
        }
    };

    stage(0, 0);
    CP_COMMIT();

    const int a_row_lane = ((lj & 1) << 3) + li;
    const int a_col_lane = (lj >> 1) << 3;
    const int b_row_lane = ((lj >> 1) << 3) + li;
    const int b_col_lane = (lj & 1) << 3;

    for (int kt = 0; kt < 16; kt++) {
        if (kt < 15) {
            stage((kt + 1) & 1, (kt + 1) * 32);
            CP_COMMIT();
            CP_WAIT(1);
        } else {
            CP_WAIT(0);
        }
        __syncthreads();

        const uint32_t base = sb + (kt & 1) * 4 * TILE_B;
        const uint32_t bAh = base, bAl = base + TILE_B;
        const uint32_t bBh = base + 2 * TILE_B, bBl = base + 3 * TILE_B;

#pragma unroll
        for (int s = 0; s < 2; s++) {
            const int kb = s * 16;
            uint32_t ah[2][4], al[2][4];
#pragma unroll
            for (int mf = 0; mf < 2; mf++) {
                uint32_t ro = (uint32_t)((wm * 32 + mf * 16 + a_row_lane) * RS
                                         + kb + a_col_lane) * 2;
                LDSM_X4(ah[mf][0], ah[mf][1], ah[mf][2], ah[mf][3], bAh + ro);
                LDSM_X4(al[mf][0], al[mf][1], al[mf][2], al[mf][3], bAl + ro);
            }
#pragma unroll
            for (int nfp = 0; nfp < 4; nfp++) {
                uint32_t ro = (uint32_t)((wn * 64 + nfp * 16 + b_row_lane) * RS
                                         + kb + b_col_lane) * 2;
                uint32_t h0, h1, h2, h3, l0, l1, l2, l3;
                LDSM_X4(h0, h1, h2, h3, bBh + ro);
                LDSM_X4(l0, l1, l2, l3, bBl + ro);
#pragma unroll
                for (int mf = 0; mf < 2; mf++) {
                    MMA_BF16(acc[mf][2 * nfp],     ah[mf], h0, h1);
                    MMA_BF16(acc[mf][2 * nfp],     ah[mf], l0, l1);
                    MMA_BF16(acc[mf][2 * nfp],     al[mf], h0, h1);
                    MMA_BF16(acc[mf][2 * nfp + 1], ah[mf], h2, h3);
                    MMA_BF16(acc[mf][2 * nfp + 1], ah[mf], l2, l3);
                    MMA_BF16(acc[mf][2 * nfp + 1], al[mf], h2, h3);
                }
            }
        }
        __syncthreads();
    }

    __nv_bfloat16 *dsth = nullptr, *dstl = nullptr;
    if (dst_sel == 0) { dsth = g_qh; dstl = g_ql; }
    else if (dst_sel == 1) { dsth = g_kh; dstl = g_kl; }
    else if (dst_sel == 2) { dsth = g_vh; dstl = g_vl; }

#pragma unroll
    for (int mf = 0; mf < 2; mf++) {
        int row = m0 + wm * 32 + mf * 16 + g;
#pragma unroll
        for (int nf = 0; nf < 8; nf++) {
            int col = n0 + wn * 64 + nf * 8 + 2 * q;
            float2 bb = *(const float2*)(bias + col);
            bb.x *= bscale;  bb.y *= bscale;
            float o0 = acc[mf][nf][0] + bb.x, o1 = acc[mf][nf][1] + bb.y;
            float o2 = acc[mf][nf][2] + bb.x, o3 = acc[mf][nf][3] + bb.y;
            if (dst_sel < 0) {
                *(float2*)(Cext + (size_t)row * DIM + col)       = make_float2(o0, o1);
                *(float2*)(Cext + (size_t)(row + 8) * DIM + col) = make_float2(o2, o3);
            } else {
                float h0 = __bfloat162float(__float2bfloat16(o0));
                float h1 = __bfloat162float(__float2bfloat16(o1));
                float h2 = __bfloat162float(__float2bfloat16(o2));
                float h3 = __bfloat162float(__float2bfloat16(o3));
                *(uint32_t*)(dsth + (size_t)row * DIM + col)       = pack_bf16(h0, h1);
                *(uint32_t*)(dsth + (size_t)(row + 8) * DIM + col) = pack_bf16(h2, h3);
                *(uint32_t*)(dstl + (size_t)row * DIM + col)       = pack_bf16(o0 - h0, o1 - h1);
                *(uint32_t*)(dstl + (size_t)(row + 8) * DIM + col) = pack_bf16(o2 - h2, o3 - h3);
            }
        }
    }
}

// ---------------------------------------------------------------------------
// Flash attention via mma.sync, bf16x3 both matmuls, ldmatrix loads.
// V is staged in K-layout (seq x dh) and PV B-fragments come from
// ldmatrix.x4.trans — no V transpose kernel, no V^T gmem roundtrip.
// ---------------------------------------------------------------------------
#define AKS 72
#define ATILE (64 * AKS * 2)              // 9216 B per array
#define ASTG  (4 * ATILE)                 // 36864 per stage
#define ASM_TOTAL (2 * ASTG)              // 73728

__global__ void __launch_bounds__(256, 2) attn_mma_kernel()
{
    extern __shared__ char smem[];
    const uint32_t sb = smem_u32(smem);
    const int tid  = threadIdx.x;
    const int wid  = tid >> 5;
    const int lane = tid & 31;
    const int g    = lane >> 2;
    const int q    = lane & 3;
    const int lj   = lane >> 3;
    const int li   = lane & 7;
    const int n    = blockIdx.y;
    const int qt   = blockIdx.x;

    const size_t nb = (size_t)n * 65536;
    const __nv_bfloat16* qhp = g_qh + nb + (qt * 128) * 64;
    const __nv_bfloat16* qlp = g_ql + nb + (qt * 128) * 64;

    uint32_t qah[4][4], qal[4][4];
    const int r0 = wid * 16 + g, r1 = r0 + 8;
#pragma unroll
    for (int ks = 0; ks < 4; ks++) {
        int c = ks * 16 + 2 * q;
        qah[ks][0] = *(const uint32_t*)(qhp + r0 * 64 + c);
        qah[ks][1] = *(const uint32_t*)(qhp + r1 * 64 + c);
        qah[ks][2] = *(const uint32_t*)(qhp + r0 * 64 + c + 8);
        qah[ks][3] = *(const uint32_t*)(qhp + r1 * 64 + c + 8);
        qal[ks][0] = *(const uint32_t*)(qlp + r0 * 64 + c);
        qal[ks][1] = *(const uint32_t*)(qlp + r1 * 64 + c);
        qal[ks][2] = *(const uint32_t*)(qlp + r0 * 64 + c + 8);
        qal[ks][3] = *(const uint32_t*)(qlp + r1 * 64 + c + 8);
    }

    float oacc[8][4];
#pragma unroll
    for (int i = 0; i < 8; i++)
#pragma unroll
        for (int j = 0; j < 4; j++) oacc[i][j] = 0.f;
    float m0 = -1e30f, m1 = -1e30f, l0 = 0.f, l1 = 0.f;

    // stage arrays: 0=Kh 1=Kl 2=Vh 3=Vl — all in [seq 64][dh 64] K-layout
    auto stage = [&](int buf, int kt) {
        uint32_t base = sb + buf * ASTG;
#pragma unroll
        for (int it = 0; it < 2; it++) {
            int gdx = tid + 256 * it;
            int r  = gdx >> 3;
            int qq = gdx & 7;
            uint32_t doff = (uint32_t)(r * (AKS * 2) + qq * 16);
            size_t off = nb + (size_t)(kt * 64 + r) * 64 + qq * 8;
            cp16(base + doff,             g_kh + off);
            cp16(base + ATILE + doff,     g_kl + off);
            cp16(base + 2 * ATILE + doff, g_vh + off);
            cp16(base + 3 * ATILE + doff, g_vl + off);
        }
    };

    stage(0, 0);
    CP_COMMIT();

    // K (non-trans) fragment lanes
    const int b_row_lane = ((lj >> 1) << 3) + li;
    const int b_col_lane = (lj & 1) << 3;
    // V (trans) fragment lanes: group j -> seq +((j&1)<<3), dh +((j>>1)<<3)
    const int v_row_lane = ((lj & 1) << 3) + li;
    const int v_col_lane = (lj >> 1) << 3;

    for (int kt = 0; kt < 16; kt++) {
        if (kt < 15) {
            stage((kt + 1) & 1, kt + 1);
            CP_COMMIT();
            CP_WAIT(1);
        } else {
            CP_WAIT(0);
        }
        __syncthreads();

        const uint32_t base = sb + (kt & 1) * ASTG;
        const uint32_t bKh = base, bKl = base + ATILE;
        const uint32_t bVh = base + 2 * ATILE, bVl = base + 3 * ATILE;

        float s[8][4];
#pragma unroll
        for (int nf = 0; nf < 8; nf++)
#pragma unroll
            for (int j = 0; j < 4; j++) s[nf][j] = 0.f;

#pragma unroll
        for (int ks = 0; ks < 4; ks++) {
#pragma unroll
            for (int nfp = 0; nfp < 4; nfp++) {
                uint32_t ro = (uint32_t)((nfp * 16 + b_row_lane) * AKS
                                         + ks * 16 + b_col_lane) * 2;
                uint32_t h0, h1, h2, h3, l0r, l1r, l2r, l3r;
                LDSM_X4(h0, h1, h2, h3, bKh + ro);
                LDSM_X4(l0r, l1r, l2r, l3r, bKl + ro);
                MMA_BF16(s[2 * nfp],     qah[ks], h0, h1);
                MMA_BF16(s[2 * nfp],     qah[ks], l0r, l1r);
                MMA_BF16(s[2 * nfp],     qal[ks], h0, h1);
                MMA_BF16(s[2 * nfp + 1], qah[ks], h2, h3);
                MMA_BF16(s[2 * nfp + 1], qah[ks], l2r, l3r);
                MMA_BF16(s[2 * nfp + 1], qal[ks], h2, h3);
            }
        }

        float mn0 = m0, mn1 = m1;
#pragma unroll
        for (int nf = 0; nf < 8; nf++) {
            mn0 = fmaxf(mn0, fmaxf(s[nf][0], s[nf][1]));
            mn1 = fmaxf(mn1, fmaxf(s[nf][2], s[nf][3]));
        }
#pragma unroll
        for (int off = 1; off <= 2; off <<= 1) {
            mn0 = fmaxf(mn0, __shfl_xor_sync(0xffffffffu, mn0, off));
            mn1 = fmaxf(mn1, __shfl_xor_sync(0xffffffffu, mn1, off));
        }
        float f0 = __expf(m0 - mn0), f1 = __expf(m1 - mn1);
        m0 = mn0;  m1 = mn1;

        uint32_t ph[8], ph2[8], pl[8], pl2[8];
        float ls0 = 0.f, ls1 = 0.f;
#pragma unroll
        for (int nf = 0; nf < 8; nf++) {
            float p0 = __expf(s[nf][0] - m0);
            float p1 = __expf(s[nf][1] - m0);
            float p2 = __expf(s[nf][2] - m1);
            float p3 = __expf(s[nf][3] - m1);
            ls0 += p0 + p1;  ls1 += p2 + p3;
            float h0 = __bfloat162float(__float2bfloat16(p0));
            float h1 = __bfloat162float(__float2bfloat16(p1));
            float h2 = __bfloat162float(__float2bfloat16(p2));
            float h3 = __bfloat162float(__float2bfloat16(p3));
            ph[nf]  = pack_bf16(h0, h1);
            ph2[nf] = pack_bf16(h2, h3);
            pl[nf]  = pack_bf16(p0 - h0, p1 - h1);
            pl2[nf] = pack_bf16(p2 - h2, p3 - h3);
        }
#pragma unroll
        for (int off = 1; off <= 2; off <<= 1) {
            ls0 += __shfl_xor_sync(0xffffffffu, ls0, off);
            ls1 += __shfl_xor_sync(0xffffffffu, ls1, off);
        }
        l0 = l0 * f0 + ls0;
        l1 = l1 * f1 + ls1;
#pragma unroll
        for (int dhf = 0; dhf < 8; dhf++) {
            oacc[dhf][0] *= f0;  oacc[dhf][1] *= f0;
            oacc[dhf][2] *= f1;  oacc[dhf][3] *= f1;
        }

        // O += P V, bf16x3; V fragments via ldmatrix.trans from K-layout tile
#pragma unroll
        for (int ks = 0; ks < 4; ks++) {
            uint32_t a_h[4] = {ph[2 * ks], ph2[2 * ks], ph[2 * ks + 1], ph2[2 * ks + 1]};
            uint32_t a_l[4] = {pl[2 * ks], pl2[2 * ks], pl[2 * ks + 1], pl2[2 * ks + 1]};
#pragma unroll
            for (int dhp = 0; dhp < 4; dhp++) {
                uint32_t ro = (uint32_t)((ks * 16 + v_row_lane) * AKS
                                         + dhp * 16 + v_col_lane) * 2;
                uint32_t h0, h1, h2, h3, l0r, l1r, l2r, l3r;
                LDSM_X4_T(h0, h1, h2, h3, bVh + ro);
                LDSM_X4_T(l0r, l1r, l2r, l3r, bVl + ro);
                MMA_BF16(oacc[2 * dhp],     a_h, h0, h1);
                MMA_BF16(oacc[2 * dhp],     a_h, l0r, l1r);
                MMA_BF16(oacc[2 * dhp],     a_l, h0, h1);
                MMA_BF16(oacc[2 * dhp + 1], a_h, h2, h3);
                MMA_BF16(oacc[2 * dhp + 1], a_h, l2r, l3r);
                MMA_BF16(oacc[2 * dhp + 1], a_l, h2, h3);
            }
        }
        __syncthreads();
    }

    float inv0 = 1.0f / l0, inv1 = 1.0f / l1;
    const size_t ob0 = nb + (size_t)(qt * 128 + r0) * 64;
    const size_t ob1 = nb + (size_t)(qt * 128 + r1) * 64;
#pragma unroll
    for (int dhf = 0; dhf < 8; dhf++) {
        int col = dhf * 8 + 2 * q;
        float o0 = oacc[dhf][0] * inv0, o1 = oacc[dhf][1] * inv0;
        float o2 = oacc[dhf][2] * inv1, o3 = oacc[dhf][3] * inv1;
        float h0 = __bfloat162float(__float2bfloat16(o0));
        float h1 = __bfloat162float(__float2bfloat16(o1));
        float h2 = __bfloat162float(__float2bfloat16(o2));
        float h3 = __bfloat162float(__float2bfloat16(o3));
        *(uint32_t*)(g_ah + ob0 + col) = pack_bf16(h0, h1);
        *(uint32_t*)(g_ah + ob1 + col) = pack_bf16(h2, h3);
        *(uint32_t*)(g_al + ob0 + col) = pack_bf16(o0 - h0, o1 - h1);
        *(uint32_t*)(g_al + ob1 + col) = pack_bf16(o2 - h2, o3 - h3);
    }
}

// ---------------------------------------------------------------------------
extern "C" void kernel_launch(void* const* d_in, const int* in_sizes, int n_in,
                              void* d_out, int out_size)
{
    const float* x  = (const float*)d_in[0];
    const float* wq = (const float*)d_in[1];
    const float* bq = (const float*)d_in[2];
    const float* wk = (const float*)d_in[3];
    const float* bk = (const float*)d_in[4];
    const float* wv = (const float*)d_in[5];
    const float* bv = (const float*)d_in[6];
    const float* wo = (const float*)d_in[7];
    const float* bo = (const float*)d_in[8];
    float* out = (float*)d_out;

    static bool attr_set = false;
    if (!attr_set) {
        cudaFuncSetAttribute(gemm_mma_kernel,
                             cudaFuncAttributeMaxDynamicSharedMemorySize, GSM_TOTAL);
        cudaFuncSetAttribute(attn_mma_kernel,
                             cudaFuncAttributeMaxDynamicSharedMemorySize, ASM_TOTAL);
        attr_set = true;
    }

    prep_w_kernel<<<dim3(1024, 4), 256>>>(wq, wk, wv, wo);
    split_x_kernel<<<8192, 256>>>(x);

    // Fused Q/K/V projections (round-9 config): blockIdx.z selects weight+dst
    gemm_mma_kernel<<<dim3(4, 128, 3), 256, GSM_TOTAL>>>(bq, bk, bv, nullptr, 0);

    attn_mma_kernel<<<dim3(8, NBATCH), 256, ASM_TOTAL>>>();       // O -> g_ah/g_al

    // Output projection (wsel=3, fp32 out)
    gemm_mma_kernel<<<dim3(4, 128, 1), 256, GSM_TOTAL>>>(bo, nullptr, nullptr, out, -1);
}

// round 12
// speedup vs baseline: 1.8223x; 1.0985x over previous
#include <cuda_runtime.h>
#include <cuda_bf16.h>
#include <cuda_fp16.h>
#include <cstdint>

#define MTOT 16384
#define DIM  512
#define NBATCH 128
#define SEQ 1024
#define DH 64

// Scratch (device globals = allocation-guard safe)
__device__ __align__(16) __nv_bfloat16 g_ah[MTOT * DIM];    // x split hi, later O split hi
__device__ __align__(16) __nv_bfloat16 g_al[MTOT * DIM];    // x split lo, later O split lo
__device__ __align__(16) __nv_bfloat16 g_wh[4][DIM * DIM];  // W^T hi
__device__ __align__(16) __nv_bfloat16 g_wl[4][DIM * DIM];  // W^T lo
__device__ __align__(16) __nv_bfloat16 g_qh[MTOT * DIM], g_ql[MTOT * DIM];
__device__ __align__(16) __nv_bfloat16 g_kh[MTOT * DIM], g_kl[MTOT * DIM];
__device__ __align__(16) __half g_vh[MTOT * DIM], g_vl[MTOT * DIM];   // V fp16 hi/lo

// Softmax scale with exp2 conversion folded: 0.125 * log2(e)
#define QSCALE 0.180336880111120419f

// ---------------------------------------------------------------------------
__device__ __forceinline__ uint32_t smem_u32(const void* p) {
    uint32_t a;
    asm("{ .reg .u64 t; cvta.to.shared.u64 t, %1; cvt.u32.u64 %0, t; }" : "=r"(a) : "l"(p));
    return a;
}

#define MMA_BF16(d, a, b0v, b1v)                                               \
    asm volatile("mma.sync.aligned.m16n8k16.row.col.f32.bf16.bf16.f32 "        \
                 "{%0,%1,%2,%3}, {%4,%5,%6,%7}, {%8,%9}, {%0,%1,%2,%3};"       \
                 : "+f"((d)[0]), "+f"((d)[1]), "+f"((d)[2]), "+f"((d)[3])      \
                 : "r"((a)[0]), "r"((a)[1]), "r"((a)[2]), "r"((a)[3]),         \
                   "r"(b0v), "r"(b1v))

#define MMA_FP16(d, a, b0v, b1v)                                               \
    asm volatile("mma.sync.aligned.m16n8k16.row.col.f32.f16.f16.f32 "          \
                 "{%0,%1,%2,%3}, {%4,%5,%6,%7}, {%8,%9}, {%0,%1,%2,%3};"       \
                 : "+f"((d)[0]), "+f"((d)[1]), "+f"((d)[2]), "+f"((d)[3])      \
                 : "r"((a)[0]), "r"((a)[1]), "r"((a)[2]), "r"((a)[3]),         \
                   "r"(b0v), "r"(b1v))

#define LDSM_X4(r0, r1, r2, r3, addr)                                          \
    asm volatile("ldmatrix.sync.aligned.m8n8.x4.shared.b16 {%0,%1,%2,%3}, [%4];" \
                 : "=r"(r0), "=r"(r1), "=r"(r2), "=r"(r3) : "r"(addr))

#define LDSM_X4_T(r0, r1, r2, r3, addr)                                        \
    asm volatile("ldmatrix.sync.aligned.m8n8.x4.trans.shared.b16 {%0,%1,%2,%3}, [%4];" \
                 : "=r"(r0), "=r"(r1), "=r"(r2), "=r"(r3) : "r"(addr))

__device__ __forceinline__ void cp16(uint32_t dst, const void* src) {
    asm volatile("cp.async.cg.shared.global [%0], [%1], 16;" :: "r"(dst), "l"(src) : "memory");
}
#define CP_COMMIT() asm volatile("cp.async.commit_group;" ::: "memory")
#define CP_WAIT(n)  asm volatile("cp.async.wait_group %0;" :: "n"(n) : "memory")

__device__ __forceinline__ uint32_t pack_bf16(float a, float b) {
    __nv_bfloat162 t(__float2bfloat16(a), __float2bfloat16(b));
    return *(uint32_t*)&t;
}
__device__ __forceinline__ uint32_t pack_f16(float a, float b) {
    __half2 t = __floats2half2_rn(a, b);
    return *(uint32_t*)&t;
}

// ---------------------------------------------------------------------------
// Prep: weight transposes+splits. wq absorbs QSCALE (softmax scale + log2e).
// ---------------------------------------------------------------------------
__global__ void prep_w_kernel(const float* __restrict__ w0, const float* __restrict__ w1,
                              const float* __restrict__ w2, const float* __restrict__ w3) {
    const int wsel = blockIdx.y;
    const float* W = (wsel == 0) ? w0 : (wsel == 1) ? w1 : (wsel == 2) ? w2 : w3;
    int idx = blockIdx.x * 256 + threadIdx.x;      // idx = n*512 + k
    int k = idx & (DIM - 1);
    int n = idx >> 9;
    float f = W[k * DIM + n];
    if (wsel == 0) f *= QSCALE;
    __nv_bfloat16 h = __float2bfloat16(f);
    __nv_bfloat16 l = __float2bfloat16(f - __bfloat162float(h));
    g_wh[wsel][idx] = h;
    g_wl[wsel][idx] = l;
}

__global__ void split_x_kernel(const float* __restrict__ src) {
    int i = blockIdx.x * 256 + threadIdx.x;        // 4 floats per thread
    float4 v = ((const float4*)src)[i];
    float f[4] = {v.x, v.y, v.z, v.w};
    __nv_bfloat16 h[4], l[4];
#pragma unroll
    for (int j = 0; j < 4; j++) {
        h[j] = __float2bfloat16(f[j]);
        l[j] = __float2bfloat16(f[j] - __bfloat162float(h[j]));
    }
    ((__nv_bfloat162*)g_ah)[2 * i]     = __nv_bfloat162(h[0], h[1]);
    ((__nv_bfloat162*)g_ah)[2 * i + 1] = __nv_bfloat162(h[2], h[3]);
    ((__nv_bfloat162*)g_al)[2 * i]     = __nv_bfloat162(l[0], l[1]);
    ((__nv_bfloat162*)g_al)[2 * i + 1] = __nv_bfloat162(l[2], l[3]);
}

// ---------------------------------------------------------------------------
// Tensor-core GEMM, bf16x3, ldmatrix loads. Round-9 config (128x128, 256 thr,
// 2 CTA/SM). dst_sel 2 (V) writes fp16 hi/lo for the fp16 PV path.
// ---------------------------------------------------------------------------
#define RS 40
#define TILE_B (128 * RS * 2)
#define GSM_TOTAL (2 * 4 * TILE_B)     // 81920

__global__ void __launch_bounds__(256, 2) gemm_mma_kernel(
    const float* __restrict__ bq, const float* __restrict__ bk,
    const float* __restrict__ bv, float* __restrict__ Cext, int dst_override)
{
    extern __shared__ char smem[];
    const uint32_t sb = smem_u32(smem);
    const int tid  = threadIdx.x;
    const int wid  = tid >> 5;
    const int lane = tid & 31;
    const int g    = lane >> 2;
    const int q    = lane & 3;
    const int lj   = lane >> 3;
    const int li   = lane & 7;
    const int wm   = wid >> 1;
    const int wn   = wid & 1;
    const int n0   = blockIdx.x * 128;
    const int m0   = blockIdx.y * 128;

    const int dst_sel = (dst_override < 0) ? -1 : (int)blockIdx.z;
    const int wsel    = (dst_override < 0) ? 3 : (int)blockIdx.z;
    const float* bias = (dst_override < 0) ? bq
                        : (dst_sel == 0) ? bq : (dst_sel == 1) ? bk : bv;
    const float bscale = (dst_sel == 0) ? QSCALE : 1.0f;

    const __nv_bfloat16* __restrict__ Bh = g_wh[wsel];
    const __nv_bfloat16* __restrict__ Bl = g_wl[wsel];

    float acc[2][8][4];
#pragma unroll
    for (int mf = 0; mf < 2; mf++)
#pragma unroll
        for (int nf = 0; nf < 8; nf++)
#pragma unroll
            for (int r = 0; r < 4; r++) acc[mf][nf][r] = 0.f;

    auto stage = [&](int buf, int kc) {
        uint32_t base = sb + buf * 4 * TILE_B;
#pragma unroll
        for (int it = 0; it < 2; it++) {
            int gdx = tid + 256 * it;
            int r   = gdx >> 2;
            int qq  = gdx & 3;
            uint32_t doff = (uint32_t)(r * RS * 2 + qq * 16);
            size_t aoff = (size_t)(m0 + r) * DIM + kc + qq * 8;
            size_t boff = (size_t)(n0 + r) * DIM + kc + qq * 8;
            cp16(base + doff,              g_ah + aoff);
            cp16(base + TILE_B + doff,     g_al + aoff);
            cp16(base + 2 * TILE_B + doff, Bh + boff);
            cp16(base + 3 * TILE_B + doff, Bl + boff);
        }
    };

    stage(0, 0);
    CP_COMMIT();

    const int a_row_lane = ((lj & 1) << 3) + li;
    const int a_col_lane = (lj >> 1) << 3;
    const int b_row_lane = ((lj >> 1) << 3) + li;
    const int b_col_lane = (lj & 1) << 3;

    for (int kt = 0; kt < 16; kt++) {
        if (kt < 15) {
            stage((kt + 1) & 1, (kt + 1) * 32);
            CP_COMMIT();
            CP_WAIT(1);
        } else {
            CP_WAIT(0);
        }
        __syncthreads();

        const uint32_t base = sb + (kt & 1) * 4 * TILE_B;
        const uint32_t bAh = base, bAl = base + TILE_B;
        const uint32_t bBh = base + 2 * TILE_B, bBl = base + 3 * TILE_B;

#pragma unroll
        for (int s = 0; s < 2; s++) {
            const int kb = s * 16;
            uint32_t ah[2][4], al[2][4];
#pragma unroll
            for (int mf = 0; mf < 2; mf++) {
                uint32_t ro = (uint32_t)((wm * 32 + mf * 16 + a_row_lane) * RS
                                         + kb + a_col_lane) * 2;
                LDSM_X4(ah[mf][0], ah[mf][1], ah[mf][2], ah[mf][3], bAh + ro);
                LDSM_X4(al[mf][0], al[mf][1], al[mf][2], al[mf][3], bAl + ro);
            }
#pragma unroll
            for (int nfp = 0; nfp < 4; nfp++) {
                uint32_t ro = (uint32_t)((wn * 64 + nfp * 16 + b_row_lane) * RS
                                         + kb + b_col_lane) * 2;
                uint32_t h0, h1, h2, h3, l0, l1, l2, l3;
                LDSM_X4(h0, h1, h2, h3, bBh + ro);
                LDSM_X4(l0, l1, l2, l3, bBl + ro);
#pragma unroll
                for (int mf = 0; mf < 2; mf++) {
                    MMA_BF16(acc[mf][2 * nfp],     ah[mf], h0, h1);
                    MMA_BF16(acc[mf][2 * nfp],     ah[mf], l0, l1);
                    MMA_BF16(acc[mf][2 * nfp],     al[mf], h0, h1);
                    MMA_BF16(acc[mf][2 * nfp + 1], ah[mf], h2, h3);
                    MMA_BF16(acc[mf][2 * nfp + 1], ah[mf], l2, l3);
                    MMA_BF16(acc[mf][2 * nfp + 1], al[mf], h2, h3);
                }
            }
        }
        __syncthreads();
    }

#pragma unroll
    for (int mf = 0; mf < 2; mf++) {
        int row = m0 + wm * 32 + mf * 16 + g;
#pragma unroll
        for (int nf = 0; nf < 8; nf++) {
            int col = n0 + wn * 64 + nf * 8 + 2 * q;
            float2 bb = *(const float2*)(bias + col);
            bb.x *= bscale;  bb.y *= bscale;
            float o0 = acc[mf][nf][0] + bb.x, o1 = acc[mf][nf][1] + bb.y;
            float o2 = acc[mf][nf][2] + bb.x, o3 = acc[mf][nf][3] + bb.y;
            if (dst_sel < 0) {
                *(float2*)(Cext + (size_t)row * DIM + col)       = make_float2(o0, o1);
                *(float2*)(Cext + (size_t)(row + 8) * DIM + col) = make_float2(o2, o3);
            } else if (dst_sel == 2) {
                // V: fp16 hi/lo split
                float h0 = __half2float(__float2half_rn(o0));
                float h1 = __half2float(__float2half_rn(o1));
                float h2 = __half2float(__float2half_rn(o2));
                float h3 = __half2float(__float2half_rn(o3));
                *(uint32_t*)(g_vh + (size_t)row * DIM + col)       = pack_f16(o0, o1);
                *(uint32_t*)(g_vh + (size_t)(row + 8) * DIM + col) = pack_f16(o2, o3);
                *(uint32_t*)(g_vl + (size_t)row * DIM + col)       = pack_f16(o0 - h0, o1 - h1);
                *(uint32_t*)(g_vl + (size_t)(row + 8) * DIM + col) = pack_f16(o2 - h2, o3 - h3);
            } else {
                __nv_bfloat16* dsth = (dst_sel == 0) ? g_qh : g_kh;
                __nv_bfloat16* dstl = (dst_sel == 0) ? g_ql : g_kl;
                float h0 = __bfloat162float(__float2bfloat16(o0));
                float h1 = __bfloat162float(__float2bfloat16(o1));
                float h2 = __bfloat162float(__float2bfloat16(o2));
                float h3 = __bfloat162float(__float2bfloat16(o3));
                *(uint32_t*)(dsth + (size_t)row * DIM + col)       = pack_bf16(h0, h1);
                *(uint32_t*)(dsth + (size_t)(row + 8) * DIM + col) = pack_bf16(h2, h3);
                *(uint32_t*)(dstl + (size_t)row * DIM + col)       = pack_bf16(o0 - h0, o1 - h1);
                *(uint32_t*)(dstl + (size_t)(row + 8) * DIM + col) = pack_bf16(o2 - h2, o3 - h3);
            }
        }
    }
}

// ---------------------------------------------------------------------------
// Flash attention: S = QK^T bf16x3 (pre-scaled by QSCALE -> exp2 softmax);
// PV = Ph_fp16 * (Vh + Vl)_fp16 (2 terms; P ulp 2^-11 -> est ~2e-4 rel err).
// ---------------------------------------------------------------------------
#define AKS 72
#define ATILE (64 * AKS * 2)              // 9216 B per array
#define ASTG  (4 * ATILE)                 // 36864 per stage
#define ASM_TOTAL (2 * ASTG)              // 73728

__global__ void __launch_bounds__(256, 2) attn_mma_kernel()
{
    extern __shared__ char smem[];
    const uint32_t sb = smem_u32(smem);
    const int tid  = threadIdx.x;
    const int wid  = tid >> 5;
    const int lane = tid & 31;
    const int g    = lane >> 2;
    const int q    = lane & 3;
    const int lj   = lane >> 3;
    const int li   = lane & 7;
    const int n    = blockIdx.y;
    const int qt   = blockIdx.x;

    const size_t nb = (size_t)n * 65536;
    const __nv_bfloat16* qhp = g_qh + nb + (qt * 128) * 64;
    const __nv_bfloat16* qlp = g_ql + nb + (qt * 128) * 64;

    uint32_t qah[4][4], qal[4][4];
    const int r0 = wid * 16 + g, r1 = r0 + 8;
#pragma unroll
    for (int ks = 0; ks < 4; ks++) {
        int c = ks * 16 + 2 * q;
        qah[ks][0] = *(const uint32_t*)(qhp + r0 * 64 + c);
        qah[ks][1] = *(const uint32_t*)(qhp + r1 * 64 + c);
        qah[ks][2] = *(const uint32_t*)(qhp + r0 * 64 + c + 8);
        qah[ks][3] = *(const uint32_t*)(qhp + r1 * 64 + c + 8);
        qal[ks][0] = *(const uint32_t*)(qlp + r0 * 64 + c);
        qal[ks][1] = *(const uint32_t*)(qlp + r1 * 64 + c);
        qal[ks][2] = *(const uint32_t*)(qlp + r0 * 64 + c + 8);
        qal[ks][3] = *(const uint32_t*)(qlp + r1 * 64 + c + 8);
    }

    float oacc[8][4];
#pragma unroll
    for (int i = 0; i < 8; i++)
#pragma unroll
        for (int j = 0; j < 4; j++) oacc[i][j] = 0.f;
    float m0 = -1e30f, m1 = -1e30f, l0 = 0.f, l1 = 0.f;

    // stage arrays: 0=Kh(bf16) 1=Kl(bf16) 2=Vh(fp16) 3=Vl(fp16), [seq][dh]
    auto stage = [&](int buf, int kt) {
        uint32_t base = sb + buf * ASTG;
#pragma unroll
        for (int it = 0; it < 2; it++) {
            int gdx = tid + 256 * it;
            int r  = gdx >> 3;
            int qq = gdx & 7;
            uint32_t doff = (uint32_t)(r * (AKS * 2) + qq * 16);
            size_t off = nb + (size_t)(kt * 64 + r) * 64 + qq * 8;
            cp16(base + doff,             g_kh + off);
            cp16(base + ATILE + doff,     g_kl + off);
            cp16(base + 2 * ATILE + doff, g_vh + off);
            cp16(base + 3 * ATILE + doff, g_vl + off);
        }
    };

    stage(0, 0);
    CP_COMMIT();

    const int b_row_lane = ((lj >> 1) << 3) + li;
    const int b_col_lane = (lj & 1) << 3;
    const int v_row_lane = ((lj & 1) << 3) + li;
    const int v_col_lane = (lj >> 1) << 3;

    for (int kt = 0; kt < 16; kt++) {
        if (kt < 15) {
            stage((kt + 1) & 1, kt + 1);
            CP_COMMIT();
            CP_WAIT(1);
        } else {
            CP_WAIT(0);
        }
        __syncthreads();

        const uint32_t base = sb + (kt & 1) * ASTG;
        const uint32_t bKh = base, bKl = base + ATILE;
        const uint32_t bVh = base + 2 * ATILE, bVl = base + 3 * ATILE;

        float s[8][4];
#pragma unroll
        for (int nf = 0; nf < 8; nf++)
#pragma unroll
            for (int j = 0; j < 4; j++) s[nf][j] = 0.f;

#pragma unroll
        for (int ks = 0; ks < 4; ks++) {
#pragma unroll
            for (int nfp = 0; nfp < 4; nfp++) {
                uint32_t ro = (uint32_t)((nfp * 16 + b_row_lane) * AKS
                                         + ks * 16 + b_col_lane) * 2;
                uint32_t h0, h1, h2, h3, l0r, l1r, l2r, l3r;
                LDSM_X4(h0, h1, h2, h3, bKh + ro);
                LDSM_X4(l0r, l1r, l2r, l3r, bKl + ro);
                MMA_BF16(s[2 * nfp],     qah[ks], h0, h1);
                MMA_BF16(s[2 * nfp],     qah[ks], l0r, l1r);
                MMA_BF16(s[2 * nfp],     qal[ks], h0, h1);
                MMA_BF16(s[2 * nfp + 1], qah[ks], h2, h3);
                MMA_BF16(s[2 * nfp + 1], qah[ks], l2r, l3r);
                MMA_BF16(s[2 * nfp + 1], qal[ks], h2, h3);
            }
        }

        float mn0 = m0, mn1 = m1;
#pragma unroll
        for (int nf = 0; nf < 8; nf++) {
            mn0 = fmaxf(mn0, fmaxf(s[nf][0], s[nf][1]));
            mn1 = fmaxf(mn1, fmaxf(s[nf][2], s[nf][3]));
        }
#pragma unroll
        for (int off = 1; off <= 2; off <<= 1) {
            mn0 = fmaxf(mn0, __shfl_xor_sync(0xffffffffu, mn0, off));
            mn1 = fmaxf(mn1, __shfl_xor_sync(0xffffffffu, mn1, off));
        }
        float f0 = exp2f(m0 - mn0), f1 = exp2f(m1 - mn1);
        m0 = mn0;  m1 = mn1;

        uint32_t ph[8], ph2[8];
        float ls0 = 0.f, ls1 = 0.f;
#pragma unroll
        for (int nf = 0; nf < 8; nf++) {
            float p0 = exp2f(s[nf][0] - m0);
            float p1 = exp2f(s[nf][1] - m0);
            float p2 = exp2f(s[nf][2] - m1);
            float p3 = exp2f(s[nf][3] - m1);
            ls0 += p0 + p1;  ls1 += p2 + p3;
            ph[nf]  = pack_f16(p0, p1);
            ph2[nf] = pack_f16(p2, p3);
        }
#pragma unroll
        for (int off = 1; off <= 2; off <<= 1) {
            ls0 += __shfl_xor_sync(0xffffffffu, ls0, off);
            ls1 += __shfl_xor_sync(0xffffffffu, ls1, off);
        }
        l0 = l0 * f0 + ls0;
        l1 = l1 * f1 + ls1;
#pragma unroll
        for (int dhf = 0; dhf < 8; dhf++) {
            oacc[dhf][0] *= f0;  oacc[dhf][1] *= f0;
            oacc[dhf][2] *= f1;  oacc[dhf][3] *= f1;
        }

        // O += Ph (Vh + Vl), fp16 mma, V via ldmatrix.trans
#pragma unroll
        for (int ks = 0; ks < 4; ks++) {
            uint32_t a_h[4] = {ph[2 * ks], ph2[2 * ks], ph[2 * ks + 1], ph2[2 * ks + 1]};
#pragma unroll
            for (int dhp = 0; dhp < 4; dhp++) {
                uint32_t ro = (uint32_t)((ks * 16 + v_row_lane) * AKS
                                         + dhp * 16 + v_col_lane) * 2;
                uint32_t h0, h1, h2, h3, l0r, l1r, l2r, l3r;
                LDSM_X4_T(h0, h1, h2, h3, bVh + ro);
                LDSM_X4_T(l0r, l1r, l2r, l3r, bVl + ro);
                MMA_FP16(oacc[2 * dhp],     a_h, h0, h1);
                MMA_FP16(oacc[2 * dhp],     a_h, l0r, l1r);
                MMA_FP16(oacc[2 * dhp + 1], a_h, h2, h3);
                MMA_FP16(oacc[2 * dhp + 1], a_h, l2r, l3r);
            }
        }
        __syncthreads();
    }

    float inv0 = 1.0f / l0, inv1 = 1.0f / l1;
    const size_t ob0 = nb + (size_t)(qt * 128 + r0) * 64;
    const size_t ob1 = nb + (size_t)(qt * 128 + r1) * 64;
#pragma unroll
    for (int dhf = 0; dhf < 8; dhf++) {
        int col = dhf * 8 + 2 * q;
        float o0 = oacc[dhf][0] * inv0, o1 = oacc[dhf][1] * inv0;
        float o2 = oacc[dhf][2] * inv1, o3 = oacc[dhf][3] * inv1;
        float h0 = __bfloat162float(__float2bfloat16(o0));
        float h1 = __bfloat162float(__float2bfloat16(o1));
        float h2 = __bfloat162float(__float2bfloat16(o2));
        float h3 = __bfloat162float(__float2bfloat16(o3));
        *(uint32_t*)(g_ah + ob0 + col) = pack_bf16(h0, h1);
        *(uint32_t*)(g_ah + ob1 + col) = pack_bf16(h2, h3);
        *(uint32_t*)(g_al + ob0 + col) = pack_bf16(o0 - h0, o1 - h1);
        *(uint32_t*)(g_al + ob1 + col) = pack_bf16(o2 - h2, o3 - h3);
    }
}

// ---------------------------------------------------------------------------
extern "C" void kernel_launch(void* const* d_in, const int* in_sizes, int n_in,
                              void* d_out, int out_size)
{
    const float* x  = (const float*)d_in[0];
    const float* wq = (const float*)d_in[1];
    const float* bq = (const float*)d_in[2];
    const float* wk = (const float*)d_in[3];
    const float* bk = (const float*)d_in[4];
    const float* wv = (const float*)d_in[5];
    const float* bv = (const float*)d_in[6];
    const float* wo = (const float*)d_in[7];
    const float* bo = (const float*)d_in[8];
    float* out = (float*)d_out;

    static bool attr_set = false;
    if (!attr_set) {
        cudaFuncSetAttribute(gemm_mma_kernel,
                             cudaFuncAttributeMaxDynamicSharedMemorySize, GSM_TOTAL);
        cudaFuncSetAttribute(attn_mma_kernel,
                             cudaFuncAttributeMaxDynamicSharedMemorySize, ASM_TOTAL);
        attr_set = true;
    }

    prep_w_kernel<<<dim3(1024, 4), 256>>>(wq, wk, wv, wo);
    split_x_kernel<<<8192, 256>>>(x);

    // Fused Q/K/V projections: blockIdx.z selects weight + destination
    gemm_mma_kernel<<<dim3(4, 128, 3), 256, GSM_TOTAL>>>(bq, bk, bv, nullptr, 0);

    attn_mma_kernel<<<dim3(8, NBATCH), 256, ASM_TOTAL>>>();       // O -> g_ah/g_al

    // Output projection (wsel=3, fp32 out)
    gemm_mma_kernel<<<dim3(4, 128, 1), 256, GSM_TOTAL>>>(bo, nullptr, nullptr, out, -1);
}

// round 15
// speedup vs baseline: 1.8573x; 1.0192x over previous
#include <cuda_runtime.h>
#include <cuda_bf16.h>
#include <cuda_fp16.h>
#include <cstdint>

#define MTOT 16384
#define DIM  512
#define NBATCH 128
#define SEQ 1024
#define DH 64

// Scratch (device globals = allocation-guard safe)
__device__ __align__(16) __nv_bfloat16 g_ah[MTOT * DIM];    // x split hi, later O split hi
__device__ __align__(16) __nv_bfloat16 g_al[MTOT * DIM];    // x split lo, later O split lo
__device__ __align__(16) __nv_bfloat16 g_wh[4][DIM * DIM];  // W^T hi
__device__ __align__(16) __nv_bfloat16 g_wl[4][DIM * DIM];  // W^T lo
__device__ __align__(16) __nv_bfloat16 g_qh[MTOT * DIM], g_ql[MTOT * DIM];
__device__ __align__(16) __nv_bfloat16 g_kh[MTOT * DIM], g_kl[MTOT * DIM];
__device__ __align__(16) __half g_vh[MTOT * DIM], g_vl[MTOT * DIM];   // V fp16 hi/lo

// Softmax scale with exp2 conversion folded: 0.125 * log2(e)
#define QSCALE 0.180336880111120419f

// ---------------------------------------------------------------------------
__device__ __forceinline__ uint32_t smem_u32(const void* p) {
    uint32_t a;
    asm("{ .reg .u64 t; cvta.to.shared.u64 t, %1; cvt.u32.u64 %0, t; }" : "=r"(a) : "l"(p));
    return a;
}

// MUFU exp2 (single EX2 instruction; <=2 ulp, negligible vs fp16 P rounding)
__device__ __forceinline__ float ex2(float x) {
    float y;
    asm("ex2.approx.ftz.f32 %0, %1;" : "=f"(y) : "f"(x));
    return y;
}
__device__ __forceinline__ float frcp(float x) {
    float y;
    asm("rcp.approx.ftz.f32 %0, %1;" : "=f"(y) : "f"(x));
    return y;
}

#define MMA_BF16(d, a, b0v, b1v)                                               \
    asm volatile("mma.sync.aligned.m16n8k16.row.col.f32.bf16.bf16.f32 "        \
                 "{%0,%1,%2,%3}, {%4,%5,%6,%7}, {%8,%9}, {%0,%1,%2,%3};"       \
                 : "+f"((d)[0]), "+f"((d)[1]), "+f"((d)[2]), "+f"((d)[3])      \
                 : "r"((a)[0]), "r"((a)[1]), "r"((a)[2]), "r"((a)[3]),         \
                   "r"(b0v), "r"(b1v))

#define MMA_FP16(d, a, b0v, b1v)                                               \
    asm volatile("mma.sync.aligned.m16n8k16.row.col.f32.f16.f16.f32 "          \
                 "{%0,%1,%2,%3}, {%4,%5,%6,%7}, {%8,%9}, {%0,%1,%2,%3};"       \
                 : "+f"((d)[0]), "+f"((d)[1]), "+f"((d)[2]), "+f"((d)[3])      \
                 : "r"((a)[0]), "r"((a)[1]), "r"((a)[2]), "r"((a)[3]),         \
                   "r"(b0v), "r"(b1v))

#define LDSM_X4(r0, r1, r2, r3, addr)                                          \
    asm volatile("ldmatrix.sync.aligned.m8n8.x4.shared.b16 {%0,%1,%2,%3}, [%4];" \
                 : "=r"(r0), "=r"(r1), "=r"(r2), "=r"(r3) : "r"(addr))

#define LDSM_X4_T(r0, r1, r2, r3, addr)                                        \
    asm volatile("ldmatrix.sync.aligned.m8n8.x4.trans.shared.b16 {%0,%1,%2,%3}, [%4];" \
                 : "=r"(r0), "=r"(r1), "=r"(r2), "=r"(r3) : "r"(addr))

__device__ __forceinline__ void cp16(uint32_t dst, const void* src) {
    asm volatile("cp.async.cg.shared.global [%0], [%1], 16;" :: "r"(dst), "l"(src) : "memory");
}
#define CP_COMMIT() asm volatile("cp.async.commit_group;" ::: "memory")
#define CP_WAIT(n)  asm volatile("cp.async.wait_group %0;" :: "n"(n) : "memory")

__device__ __forceinline__ uint32_t pack_bf16(float a, float b) {
    __nv_bfloat162 t(__float2bfloat16(a), __float2bfloat16(b));
    return *(uint32_t*)&t;
}
__device__ __forceinline__ uint32_t pack_f16(float a, float b) {
    __half2 t = __floats2half2_rn(a, b);
    return *(uint32_t*)&t;
}

// ---------------------------------------------------------------------------
// Fused prep: blocks [0,4096) transpose+split the 4 weights (wq absorbs
// QSCALE); blocks [4096,12288) split x into bf16 hi/lo.
// ---------------------------------------------------------------------------
__global__ void prep_all_kernel(const float* __restrict__ w0, const float* __restrict__ w1,
                                const float* __restrict__ w2, const float* __restrict__ w3,
                                const float* __restrict__ x) {
    int b = blockIdx.x;
    if (b < 4096) {
        int wsel = b >> 10;                        // 1024 blocks per weight
        const float* W = (wsel == 0) ? w0 : (wsel == 1) ? w1 : (wsel == 2) ? w2 : w3;
        int idx = (b & 1023) * 256 + threadIdx.x;  // idx = n*512 + k
        int k = idx & (DIM - 1);
        int n = idx >> 9;
        float f = W[k * DIM + n];
        if (wsel == 0) f *= QSCALE;
        __nv_bfloat16 h = __float2bfloat16(f);
        __nv_bfloat16 l = __float2bfloat16(f - __bfloat162float(h));
        g_wh[wsel][idx] = h;
        g_wl[wsel][idx] = l;
    } else {
        int i = (b - 4096) * 256 + threadIdx.x;    // 4 floats per thread
        float4 v = ((const float4*)x)[i];
        float f[4] = {v.x, v.y, v.z, v.w};
        __nv_bfloat16 h[4], l[4];
#pragma unroll
        for (int j = 0; j < 4; j++) {
            h[j] = __float2bfloat16(f[j]);
            l[j] = __float2bfloat16(f[j] - __bfloat162float(h[j]));
        }
        ((__nv_bfloat162*)g_ah)[2 * i]     = __nv_bfloat162(h[0], h[1]);
        ((__nv_bfloat162*)g_ah)[2 * i + 1] = __nv_bfloat162(h[2], h[3]);
        ((__nv_bfloat162*)g_al)[2 * i]     = __nv_bfloat162(l[0], l[1]);
        ((__nv_bfloat162*)g_al)[2 * i + 1] = __nv_bfloat162(l[2], l[3]);
    }
}

// ---------------------------------------------------------------------------
// Tensor-core GEMM, bf16x3, ldmatrix loads. Round-9 config (128x128, 256 thr,
// 2 CTA/SM). dst_sel 2 (V) writes fp16 hi/lo for the fp16 PV path.
// ---------------------------------------------------------------------------
#define RS 40
#define TILE_B (128 * RS * 2)
#define GSM_TOTAL (2 * 4 * TILE_B)     // 81920

__global__ void __launch_bounds__(256, 2) gemm_mma_kernel(
    const float* __restrict__ bq, const float* __restrict__ bk,
    const float* __restrict__ bv, float* __restrict__ Cext, int dst_override)
{
    extern __shared__ char smem[];
    const uint32_t sb = smem_u32(smem);
    const int tid  = threadIdx.x;
    const int wid  = tid >> 5;
    const int lane = tid & 31;
    const int g    = lane >> 2;
    const int q    = lane & 3;
    const int lj   = lane >> 3;
    const int li   = lane & 7;
    const int wm   = wid >> 1;
    const int wn   = wid & 1;
    const int n0   = blockIdx.x * 128;
    const int m0   = blockIdx.y * 128;

    const int dst_sel = (dst_override < 0) ? -1 : (int)blockIdx.z;
    const int wsel    = (dst_override < 0) ? 3 : (int)blockIdx.z;
    const float* bias = (dst_override < 0) ? bq
                        : (dst_sel == 0) ? bq : (dst_sel == 1) ? bk : bv;
    const float bscale = (dst_sel == 0) ? QSCALE : 1.0f;

    const __nv_bfloat16* __restrict__ Bh = g_wh[wsel];
    const __nv_bfloat16* __restrict__ Bl = g_wl[wsel];

    float acc[2][8][4];
#pragma unroll
    for (int mf = 0; mf < 2; mf++)
#pragma unroll
        for (int nf = 0; nf < 8; nf++)
#pragma unroll
            for (int r = 0; r < 4; r++) acc[mf][nf][r] = 0.f;

    auto stage = [&](int buf, int kc) {
        uint32_t base = sb + buf * 4 * TILE_B;
#pragma unroll
        for (int it = 0; it < 2; it++) {
            int gdx = tid + 256 * it;
            int r   = gdx >> 2;
            int qq  = gdx & 3;
            uint32_t doff = (uint32_t)(r * RS * 2 + qq * 16);
            size_t aoff = (size_t)(m0 + r) * DIM + kc + qq * 8;
            size_t boff = (size_t)(n0 + r) * DIM + kc + qq * 8;
            cp16(base + doff,              g_ah + aoff);
            cp16(base + TILE_B + doff,     g_al + aoff);
            cp16(base + 2 * TILE_B + doff, Bh + boff);
            cp16(base + 3 * TILE_B + doff, Bl + boff);
        }
    };

    stage(0, 0);
    CP_COMMIT();

    const int a_row_lane = ((lj & 1) << 3) + li;
    const int a_col_lane = (lj >> 1) << 3;
    const int b_row_lane = ((lj >> 1) << 3) + li;
    const int b_col_lane = (lj & 1) << 3;

    for (int kt = 0; kt < 16; kt++) {
        if (kt < 15) {
            stage((kt + 1) & 1, (kt + 1) * 32);
            CP_COMMIT();
            CP_WAIT(1);
        } else {
            CP_WAIT(0);
        }
        __syncthreads();

        const uint32_t base = sb + (kt & 1) * 4 * TILE_B;
        const uint32_t bAh = base, bAl = base + TILE_B;
        const uint32_t bBh = base + 2 * TILE_B, bBl = base + 3 * TILE_B;

#pragma unroll
        for (int s = 0; s < 2; s++) {
            const int kb = s * 16;
            uint32_t ah[2][4], al[2][4];
#pragma unroll
            for (int mf = 0; mf < 2; mf++) {
                uint32_t ro = (uint32_t)((wm * 32 + mf * 16 + a_row_lane) * RS
                                         + kb + a_col_lane) * 2;
                LDSM_X4(ah[mf][0], ah[mf][1], ah[mf][2], ah[mf][3], bAh + ro);
                LDSM_X4(al[mf][0], al[mf][1], al[mf][2], al[mf][3], bAl + ro);
            }
#pragma unroll
            for (int nfp = 0; nfp < 4; nfp++) {
                uint32_t ro = (uint32_t)((wn * 64 + nfp * 16 + b_row_lane) * RS
                                         + kb + b_col_lane) * 2;
                uint32_t h0, h1, h2, h3, l0, l1, l2, l3;
                LDSM_X4(h0, h1, h2, h3, bBh + ro);
                LDSM_X4(l0, l1, l2, l3, bBl + ro);
#pragma unroll
                for (int mf = 0; mf < 2; mf++) {
                    MMA_BF16(acc[mf][2 * nfp],     ah[mf], h0, h1);
                    MMA_BF16(acc[mf][2 * nfp],     ah[mf], l0, l1);
                    MMA_BF16(acc[mf][2 * nfp],     al[mf], h0, h1);
                    MMA_BF16(acc[mf][2 * nfp + 1], ah[mf], h2, h3);
                    MMA_BF16(acc[mf][2 * nfp + 1], ah[mf], l2, l3);
                    MMA_BF16(acc[mf][2 * nfp + 1], al[mf], h2, h3);
                }
            }
        }
        __syncthreads();
    }

#pragma unroll
    for (int mf = 0; mf < 2; mf++) {
        int row = m0 + wm * 32 + mf * 16 + g;
#pragma unroll
        for (int nf = 0; nf < 8; nf++) {
            int col = n0 + wn * 64 + nf * 8 + 2 * q;
            float2 bb = *(const float2*)(bias + col);
            bb.x *= bscale;  bb.y *= bscale;
            float o0 = acc[mf][nf][0] + bb.x, o1 = acc[mf][nf][1] + bb.y;
            float o2 = acc[mf][nf][2] + bb.x, o3 = acc[mf][nf][3] + bb.y;
            if (dst_sel < 0) {
                *(float2*)(Cext + (size_t)row * DIM + col)       = make_float2(o0, o1);
                *(float2*)(Cext + (size_t)(row + 8) * DIM + col) = make_float2(o2, o3);
            } else if (dst_sel == 2) {
                float h0 = __half2float(__float2half_rn(o0));
                float h1 = __half2float(__float2half_rn(o1));
                float h2 = __half2float(__float2half_rn(o2));
                float h3 = __half2float(__float2half_rn(o3));
                *(uint32_t*)(g_vh + (size_t)row * DIM + col)       = pack_f16(o0, o1);
                *(uint32_t*)(g_vh + (size_t)(row + 8) * DIM + col) = pack_f16(o2, o3);
                *(uint32_t*)(g_vl + (size_t)row * DIM + col)       = pack_f16(o0 - h0, o1 - h1);
                *(uint32_t*)(g_vl + (size_t)(row + 8) * DIM + col) = pack_f16(o2 - h2, o3 - h3);
            } else {
                __nv_bfloat16* dsth = (dst_sel == 0) ? g_qh : g_kh;
                __nv_bfloat16* dstl = (dst_sel == 0) ? g_ql : g_kl;
                float h0 = __bfloat162float(__float2bfloat16(o0));
                float h1 = __bfloat162float(__float2bfloat16(o1));
                float h2 = __bfloat162float(__float2bfloat16(o2));
                float h3 = __bfloat162float(__float2bfloat16(o3));
                *(uint32_t*)(dsth + (size_t)row * DIM + col)       = pack_bf16(h0, h1);
                *(uint32_t*)(dsth + (size_t)(row + 8) * DIM + col) = pack_bf16(h2, h3);
                *(uint32_t*)(dstl + (size_t)row * DIM + col)       = pack_bf16(o0 - h0, o1 - h1);
                *(uint32_t*)(dstl + (size_t)(row + 8) * DIM + col) = pack_bf16(o2 - h2, o3 - h3);
            }
        }
    }
}

// ---------------------------------------------------------------------------
// Flash attention: S = QK^T bf16x3 (QSCALE pre-folded -> exp2 softmax via
// MUFU EX2); PV = Ph_fp16 * (Vh + Vl)_fp16.
// ---------------------------------------------------------------------------
#define AKS 72
#define ATILE (64 * AKS * 2)              // 9216 B per array
#define ASTG  (4 * ATILE)                 // 36864 per stage
#define ASM_TOTAL (2 * ASTG)              // 73728

__global__ void __launch_bounds__(256, 2) attn_mma_kernel()
{
    extern __shared__ char smem[];
    const uint32_t sb = smem_u32(smem);
    const int tid  = threadIdx.x;
    const int wid  = tid >> 5;
    const int lane = tid & 31;
    const int g    = lane >> 2;
    const int q    = lane & 3;
    const int lj   = lane >> 3;
    const int li   = lane & 7;
    const int n    = blockIdx.y;
    const int qt   = blockIdx.x;

    const size_t nb = (size_t)n * 65536;
    const __nv_bfloat16* qhp = g_qh + nb + (qt * 128) * 64;
    const __nv_bfloat16* qlp = g_ql + nb + (qt * 128) * 64;

    uint32_t qah[4][4], qal[4][4];
    const int r0 = wid * 16 + g, r1 = r0 + 8;
#pragma unroll
    for (int ks = 0; ks < 4; ks++) {
        int c = ks * 16 + 2 * q;
        qah[ks][0] = *(const uint32_t*)(qhp + r0 * 64 + c);
        qah[ks][1] = *(const uint32_t*)(qhp + r1 * 64 + c);
        qah[ks][2] = *(const uint32_t*)(qhp + r0 * 64 + c + 8);
        qah[ks][3] = *(const uint32_t*)(qhp + r1 * 64 + c + 8);
        qal[ks][0] = *(const uint32_t*)(qlp + r0 * 64 + c);
        qal[ks][1] = *(const uint32_t*)(qlp + r1 * 64 + c);
        qal[ks][2] = *(const uint32_t*)(qlp + r0 * 64 + c + 8);
        qal[ks][3] = *(const uint32_t*)(qlp + r1 * 64 + c + 8);
    }

    float oacc[8][4];
#pragma unroll
    for (int i = 0; i < 8; i++)
#pragma unroll
        for (int j = 0; j < 4; j++) oacc[i][j] = 0.f;
    float m0 = -1e30f, m1 = -1e30f, l0 = 0.f, l1 = 0.f;

    auto stage = [&](int buf, int kt) {
        uint32_t base = sb + buf * ASTG;
#pragma unroll
        for (int it = 0; it < 2; it++) {
            int gdx = tid + 256 * it;
            int r  = gdx >> 3;
            int qq = gdx & 7;
            uint32_t doff = (uint32_t)(r * (AKS * 2) + qq * 16);
            size_t off = nb + (size_t)(kt * 64 + r) * 64 + qq * 8;
            cp16(base + doff,             g_kh + off);
            cp16(base + ATILE + doff,     g_kl + off);
            cp16(base + 2 * ATILE + doff, g_vh + off);
            cp16(base + 3 * ATILE + doff, g_vl + off);
        }
    };

    stage(0, 0);
    CP_COMMIT();

    const int b_row_lane = ((lj >> 1) << 3) + li;
    const int b_col_lane = (lj & 1) << 3;
    const int v_row_lane = ((lj & 1) << 3) + li;
    const int v_col_lane = (lj >> 1) << 3;

    for (int kt = 0; kt < 16; kt++) {
        if (kt < 15) {
            stage((kt + 1) & 1, kt + 1);
            CP_COMMIT();
            CP_WAIT(1);
        } else {
            CP_WAIT(0);
        }
        __syncthreads();

        const uint32_t base = sb + (kt & 1) * ASTG;
        const uint32_t bKh = base, bKl = base + ATILE;
        const uint32_t bVh = base + 2 * ATILE, bVl = base + 3 * ATILE;

        float s[8][4];
#pragma unroll
        for (int nf = 0; nf < 8; nf++)
#pragma unroll
            for (int j = 0; j < 4; j++) s[nf][j] = 0.f;

#pragma unroll
        for (int ks = 0; ks < 4; ks++) {
#pragma unroll
            for (int nfp = 0; nfp < 4; nfp++) {
                uint32_t ro = (uint32_t)((nfp * 16 + b_row_lane) * AKS
                                         + ks * 16 + b_col_lane) * 2;
                uint32_t h0, h1, h2, h3, l0r, l1r, l2r, l3r;
                LDSM_X4(h0, h1, h2, h3, bKh + ro);
                LDSM_X4(l0r, l1r, l2r, l3r, bKl + ro);
                MMA_BF16(s[2 * nfp],     qah[ks], h0, h1);
                MMA_BF16(s[2 * nfp],     qah[ks], l0r, l1r);
                MMA_BF16(s[2 * nfp],     qal[ks], h0, h1);
                MMA_BF16(s[2 * nfp + 1], qah[ks], h2, h3);
                MMA_BF16(s[2 * nfp + 1], qah[ks], l2r, l3r);
                MMA_BF16(s[2 * nfp + 1], qal[ks], h2, h3);
            }
        }

        float mn0 = m0, mn1 = m1;
#pragma unroll
        for (int nf = 0; nf < 8; nf++) {
            mn0 = fmaxf(mn0, fmaxf(s[nf][0], s[nf][1]));
            mn1 = fmaxf(mn1, fmaxf(s[nf][2], s[nf][3]));
        }
#pragma unroll
        for (int off = 1; off <= 2; off <<= 1) {
            mn0 = fmaxf(mn0, __shfl_xor_sync(0xffffffffu, mn0, off));
            mn1 = fmaxf(mn1, __shfl_xor_sync(0xffffffffu, mn1, off));
        }
        float f0 = ex2(m0 - mn0), f1 = ex2(m1 - mn1);
        m0 = mn0;  m1 = mn1;

        uint32_t ph[8], ph2[8];
        float ls0 = 0.f, ls1 = 0.f;
#pragma unroll
        for (int nf = 0; nf < 8; nf++) {
            float p0 = ex2(s[nf][0] - m0);
            float p1 = ex2(s[nf][1] - m0);
            float p2 = ex2(s[nf][2] - m1);
            float p3 = ex2(s[nf][3] - m1);
            ls0 += p0 + p1;  ls1 += p2 + p3;
            ph[nf]  = pack_f16(p0, p1);
            ph2[nf] = pack_f16(p2, p3);
        }
#pragma unroll
        for (int off = 1; off <= 2; off <<= 1) {
            ls0 += __shfl_xor_sync(0xffffffffu, ls0, off);
            ls1 += __shfl_xor_sync(0xffffffffu, ls1, off);
        }
        l0 = l0 * f0 + ls0;
        l1 = l1 * f1 + ls1;
#pragma unroll
        for (int dhf = 0; dhf < 8; dhf++) {
            oacc[dhf][0] *= f0;  oacc[dhf][1] *= f0;
            oacc[dhf][2] *= f1;  oacc[dhf][3] *= f1;
        }

        // O += Ph (Vh + Vl), fp16 mma, V via ldmatrix.trans
#pragma unroll
        for (int ks = 0; ks < 4; ks++) {
            uint32_t a_h[4] = {ph[2 * ks], ph2[2 * ks], ph[2 * ks + 1], ph2[2 * ks + 1]};
#pragma unroll
            for (int dhp = 0; dhp < 4; dhp++) {
                uint32_t ro = (uint32_t)((ks * 16 + v_row_lane) * AKS
                                         + dhp * 16 + v_col_lane) * 2;
                uint32_t h0, h1, h2, h3, l0r, l1r, l2r, l3r;
                LDSM_X4_T(h0, h1, h2, h3, bVh + ro);
                LDSM_X4_T(l0r, l1r, l2r, l3r, bVl + ro);
                MMA_FP16(oacc[2 * dhp],     a_h, h0, h1);
                MMA_FP16(oacc[2 * dhp],     a_h, l0r, l1r);
                MMA_FP16(oacc[2 * dhp + 1], a_h, h2, h3);
                MMA_FP16(oacc[2 * dhp + 1], a_h, l2r, l3r);
            }
        }
        __syncthreads();
    }

    float inv0 = frcp(l0), inv1 = frcp(l1);
    const size_t ob0 = nb + (size_t)(qt * 128 + r0) * 64;
    const size_t ob1 = nb + (size_t)(qt * 128 + r1) * 64;
#pragma unroll
    for (int dhf = 0; dhf < 8; dhf++) {
        int col = dhf * 8 + 2 * q;
        float o0 = oacc[dhf][0] * inv0, o1 = oacc[dhf][1] * inv0;
        float o2 = oacc[dhf][2] * inv1, o3 = oacc[dhf][3] * inv1;
        float h0 = __bfloat162float(__float2bfloat16(o0));
        float h1 = __bfloat162float(__float2bfloat16(o1));
        float h2 = __bfloat162float(__float2bfloat16(o2));
        float h3 = __bfloat162float(__float2bfloat16(o3));
        *(uint32_t*)(g_ah + ob0 + col) = pack_bf16(h0, h1);
        *(uint32_t*)(g_ah + ob1 + col) = pack_bf16(h2, h3);
        *(uint32_t*)(g_al + ob0 + col) = pack_bf16(o0 - h0, o1 - h1);
        *(uint32_t*)(g_al + ob1 + col) = pack_bf16(o2 - h2, o3 - h3);
    }
}

// ---------------------------------------------------------------------------
extern "C" void kernel_launch(void* const* d_in, const int* in_sizes, int n_in,
                              void* d_out, int out_size)
{
    const float* x  = (const float*)d_in[0];
    const float* wq = (const float*)d_in[1];
    const float* bq = (const float*)d_in[2];
    const float* wk = (const float*)d_in[3];
    const float* bk = (const float*)d_in[4];
    const float* wv = (const float*)d_in[5];
    const float* bv = (const float*)d_in[6];
    const float* wo = (const float*)d_in[7];
    const float* bo = (const float*)d_in[8];
    float* out = (float*)d_out;

    static bool attr_set = false;
    if (!attr_set) {
        cudaFuncSetAttribute(gemm_mma_kernel,
                             cudaFuncAttributeMaxDynamicSharedMemorySize, GSM_TOTAL);
        cudaFuncSetAttribute(attn_mma_kernel,
                             cudaFuncAttributeMaxDynamicSharedMemorySize, ASM_TOTAL);
        attr_set = true;
    }

    prep_all_kernel<<<12288, 256>>>(wq, wk, wv, wo, x);

    // Fused Q/K/V projections: blockIdx.z selects weight + destination
    gemm_mma_kernel<<<dim3(4, 128, 3), 256, GSM_TOTAL>>>(bq, bk, bv, nullptr, 0);

    attn_mma_kernel<<<dim3(8, NBATCH), 256, ASM_TOTAL>>>();       // O -> g_ah/g_al

    // Output projection (wsel=3, fp32 out)
    gemm_mma_kernel<<<dim3(4, 128, 1), 256, GSM_TOTAL>>>(bo, nullptr, nullptr, out, -1);
}

// round 16
// speedup vs baseline: 1.8584x; 1.0006x over previous
#include <cuda_runtime.h>
#include <cuda_bf16.h>
#include <cuda_fp16.h>
#include <cstdint>

#define MTOT 16384
#define DIM  512
#define NBATCH 128
#define SEQ 1024
#define DH 64

// Scratch (device globals = allocation-guard safe)
__device__ __align__(16) __nv_bfloat16 g_ah[MTOT * DIM];    // x split hi, later O split hi
__device__ __align__(16) __nv_bfloat16 g_al[MTOT * DIM];    // x split lo, later O split lo
__device__ __align__(16) __nv_bfloat16 g_wh[4][DIM * DIM];  // W^T hi
__device__ __align__(16) __nv_bfloat16 g_wl[4][DIM * DIM];  // W^T lo
__device__ __align__(16) __nv_bfloat16 g_qh[MTOT * DIM], g_ql[MTOT * DIM];
__device__ __align__(16) __nv_bfloat16 g_kh[MTOT * DIM], g_kl[MTOT * DIM];
__device__ __align__(16) __half g_vh[MTOT * DIM], g_vl[MTOT * DIM];   // V fp16 hi/lo

// Softmax scale with exp2 conversion folded: 0.125 * log2(e)
#define QSCALE 0.180336880111120419f

// ---------------------------------------------------------------------------
__device__ __forceinline__ uint32_t smem_u32(const void* p) {
    uint32_t a;
    asm("{ .reg .u64 t; cvta.to.shared.u64 t, %1; cvt.u32.u64 %0, t; }" : "=r"(a) : "l"(p));
    return a;
}

__device__ __forceinline__ float ex2(float x) {
    float y;
    asm("ex2.approx.ftz.f32 %0, %1;" : "=f"(y) : "f"(x));
    return y;
}
__device__ __forceinline__ float frcp(float x) {
    float y;
    asm("rcp.approx.ftz.f32 %0, %1;" : "=f"(y) : "f"(x));
    return y;
}

// NOTE: mma asm is intentionally NON-volatile — pure register ops whose
// outputs are consumed; lets ptxas interleave independent mmas to break
// accumulator dependency chains (volatile pins program order).
#define MMA_BF16(d, a, b0v, b1v)                                               \
    asm("mma.sync.aligned.m16n8k16.row.col.f32.bf16.bf16.f32 "                 \
        "{%0,%1,%2,%3}, {%4,%5,%6,%7}, {%8,%9}, {%0,%1,%2,%3};"                \
        : "+f"((d)[0]), "+f"((d)[1]), "+f"((d)[2]), "+f"((d)[3])               \
        : "r"((a)[0]), "r"((a)[1]), "r"((a)[2]), "r"((a)[3]),                  \
          "r"(b0v), "r"(b1v))

#define MMA_FP16(d, a, b0v, b1v)                                               \
    asm("mma.sync.aligned.m16n8k16.row.col.f32.f16.f16.f32 "                   \
        "{%0,%1,%2,%3}, {%4,%5,%6,%7}, {%8,%9}, {%0,%1,%2,%3};"                \
        : "+f"((d)[0]), "+f"((d)[1]), "+f"((d)[2]), "+f"((d)[3])               \
        : "r"((a)[0]), "r"((a)[1]), "r"((a)[2]), "r"((a)[3]),                  \
          "r"(b0v), "r"(b1v))

#define LDSM_X4(r0, r1, r2, r3, addr)                                          \
    asm volatile("ldmatrix.sync.aligned.m8n8.x4.shared.b16 {%0,%1,%2,%3}, [%4];" \
                 : "=r"(r0), "=r"(r1), "=r"(r2), "=r"(r3) : "r"(addr))

#define LDSM_X4_T(r0, r1, r2, r3, addr)                                        \
    asm volatile("ldmatrix.sync.aligned.m8n8.x4.trans.shared.b16 {%0,%1,%2,%3}, [%4];" \
                 : "=r"(r0), "=r"(r1), "=r"(r2), "=r"(r3) : "r"(addr))

__device__ __forceinline__ void cp16(uint32_t dst, const void* src) {
    asm volatile("cp.async.cg.shared.global [%0], [%1], 16;" :: "r"(dst), "l"(src) : "memory");
}
#define CP_COMMIT() asm volatile("cp.async.commit_group;" ::: "memory")
#define CP_WAIT(n)  asm volatile("cp.async.wait_group %0;" :: "n"(n) : "memory")

__device__ __forceinline__ uint32_t pack_bf16(float a, float b) {
    __nv_bfloat162 t(__float2bfloat16(a), __float2bfloat16(b));
    return *(uint32_t*)&t;
}
__device__ __forceinline__ uint32_t pack_f16(float a, float b) {
    __half2 t = __floats2half2_rn(a, b);
    return *(uint32_t*)&t;
}

// ---------------------------------------------------------------------------
// Fused prep: blocks [0,4096) transpose+split weights (wq absorbs QSCALE);
// blocks [4096,12288) split x into bf16 hi/lo.
// ---------------------------------------------------------------------------
__global__ void prep_all_kernel(const float* __restrict__ w0, const float* __restrict__ w1,
                                const float* __restrict__ w2, const float* __restrict__ w3,
                                const float* __restrict__ x) {
    int b = blockIdx.x;
    if (b < 4096) {
        int wsel = b >> 10;
        const float* W = (wsel == 0) ? w0 : (wsel == 1) ? w1 : (wsel == 2) ? w2 : w3;
        int idx = (b & 1023) * 256 + threadIdx.x;  // idx = n*512 + k
        int k = idx & (DIM - 1);
        int n = idx >> 9;
        float f = W[k * DIM + n];
        if (wsel == 0) f *= QSCALE;
        __nv_bfloat16 h = __float2bfloat16(f);
        __nv_bfloat16 l = __float2bfloat16(f - __bfloat162float(h));
        g_wh[wsel][idx] = h;
        g_wl[wsel][idx] = l;
    } else {
        int i = (b - 4096) * 256 + threadIdx.x;
        float4 v = ((const float4*)x)[i];
        float f[4] = {v.x, v.y, v.z, v.w};
        __nv_bfloat16 h[4], l[4];
#pragma unroll
        for (int j = 0; j < 4; j++) {
            h[j] = __float2bfloat16(f[j]);
            l[j] = __float2bfloat16(f[j] - __bfloat162float(h[j]));
        }
        ((__nv_bfloat162*)g_ah)[2 * i]     = __nv_bfloat162(h[0], h[1]);
        ((__nv_bfloat162*)g_ah)[2 * i + 1] = __nv_bfloat162(h[2], h[3]);
        ((__nv_bfloat162*)g_al)[2 * i]     = __nv_bfloat162(l[0], l[1]);
        ((__nv_bfloat162*)g_al)[2 * i + 1] = __nv_bfloat162(l[2], l[3]);
    }
}

// ---------------------------------------------------------------------------
// Tensor-core GEMM, bf16x3, ldmatrix loads, interleaved mma issue order.
// ---------------------------------------------------------------------------
#define RS 40
#define TILE_B (128 * RS * 2)
#define GSM_TOTAL (2 * 4 * TILE_B)     // 81920

__global__ void __launch_bounds__(256, 2) gemm_mma_kernel(
    const float* __restrict__ bq, const float* __restrict__ bk,
    const float* __restrict__ bv, float* __restrict__ Cext, int dst_override)
{
    extern __shared__ char smem[];
    const uint32_t sb = smem_u32(smem);
    const int tid  = threadIdx.x;
    const int wid  = tid >> 5;
    const int lane = tid & 31;
    const int g    = lane >> 2;
    const int q    = lane & 3;
    const int lj   = lane >> 3;
    const int li   = lane & 7;
    const int wm   = wid >> 1;
    const int wn   = wid & 1;
    const int n0   = blockIdx.x * 128;
    const int m0   = blockIdx.y * 128;

    const int dst_sel = (dst_override < 0) ? -1 : (int)blockIdx.z;
    const int wsel    = (dst_override < 0) ? 3 : (int)blockIdx.z;
    const float* bias = (dst_override < 0) ? bq
                        : (dst_sel == 0) ? bq : (dst_sel == 1) ? bk : bv;
    const float bscale = (dst_sel == 0) ? QSCALE : 1.0f;

    const __nv_bfloat16* __restrict__ Bh = g_wh[wsel];
    const __nv_bfloat16* __restrict__ Bl = g_wl[wsel];

    float acc[2][8][4];
#pragma unroll
    for (int mf = 0; mf < 2; mf++)
#pragma unroll
        for (int nf = 0; nf < 8; nf++)
#pragma unroll
            for (int r = 0; r < 4; r++) acc[mf][nf][r] = 0.f;

    auto stage = [&](int buf, int kc) {
        uint32_t base = sb + buf * 4 * TILE_B;
#pragma unroll
        for (int it = 0; it < 2; it++) {
            int gdx = tid + 256 * it;
            int r   = gdx >> 2;
            int qq  = gdx & 3;
            uint32_t doff = (uint32_t)(r * RS * 2 + qq * 16);
            size_t aoff = (size_t)(m0 + r) * DIM + kc + qq * 8;
            size_t boff = (size_t)(n0 + r) * DIM + kc + qq * 8;
            cp16(base + doff,              g_ah + aoff);
            cp16(base + TILE_B + doff,     g_al + aoff);
            cp16(base + 2 * TILE_B + doff, Bh + boff);
            cp16(base + 3 * TILE_B + doff, Bl + boff);
        }
    };

    stage(0, 0);
    CP_COMMIT();

    const int a_row_lane = ((lj & 1) << 3) + li;
    const int a_col_lane = (lj >> 1) << 3;
    const int b_row_lane = ((lj >> 1) << 3) + li;
    const int b_col_lane = (lj & 1) << 3;

    for (int kt = 0; kt < 16; kt++) {
        if (kt < 15) {
            stage((kt + 1) & 1, (kt + 1) * 32);
            CP_COMMIT();
            CP_WAIT(1);
        } else {
            CP_WAIT(0);
        }
        __syncthreads();

        const uint32_t base = sb + (kt & 1) * 4 * TILE_B;
        const uint32_t bAh = base, bAl = base + TILE_B;
        const uint32_t bBh = base + 2 * TILE_B, bBl = base + 3 * TILE_B;

#pragma unroll
        for (int s = 0; s < 2; s++) {
            const int kb = s * 16;
            uint32_t ah[2][4], al[2][4];
#pragma unroll
            for (int mf = 0; mf < 2; mf++) {
                uint32_t ro = (uint32_t)((wm * 32 + mf * 16 + a_row_lane) * RS
                                         + kb + a_col_lane) * 2;
                LDSM_X4(ah[mf][0], ah[mf][1], ah[mf][2], ah[mf][3], bAh + ro);
                LDSM_X4(al[mf][0], al[mf][1], al[mf][2], al[mf][3], bAl + ro);
            }
#pragma unroll
            for (int nfp = 0; nfp < 4; nfp++) {
                uint32_t ro = (uint32_t)((wn * 64 + nfp * 16 + b_row_lane) * RS
                                         + kb + b_col_lane) * 2;
                uint32_t h0, h1, h2, h3, l0, l1, l2, l3;
                LDSM_X4(h0, h1, h2, h3, bBh + ro);
                LDSM_X4(l0, l1, l2, l3, bBl + ro);
                // Interleaved: 4 independent accumulators per term group
                MMA_BF16(acc[0][2 * nfp],     ah[0], h0, h1);
                MMA_BF16(acc[1][2 * nfp],     ah[1], h0, h1);
                MMA_BF16(acc[0][2 * nfp + 1], ah[0], h2, h3);
                MMA_BF16(acc[1][2 * nfp + 1], ah[1], h2, h3);
                MMA_BF16(acc[0][2 * nfp],     ah[0], l0, l1);
                MMA_BF16(acc[1][2 * nfp],     ah[1], l0, l1);
                MMA_BF16(acc[0][2 * nfp + 1], ah[0], l2, l3);
                MMA_BF16(acc[1][2 * nfp + 1], ah[1], l2, l3);
                MMA_BF16(acc[0][2 * nfp],     al[0], h0, h1);
                MMA_BF16(acc[1][2 * nfp],     al[1], h0, h1);
                MMA_BF16(acc[0][2 * nfp + 1], al[0], h2, h3);
                MMA_BF16(acc[1][2 * nfp + 1], al[1], h2, h3);
            }
        }
        __syncthreads();
    }

#pragma unroll
    for (int mf = 0; mf < 2; mf++) {
        int row = m0 + wm * 32 + mf * 16 + g;
#pragma unroll
        for (int nf = 0; nf < 8; nf++) {
            int col = n0 + wn * 64 + nf * 8 + 2 * q;
            float2 bb = *(const float2*)(bias + col);
            bb.x *= bscale;  bb.y *= bscale;
            float o0 = acc[mf][nf][0] + bb.x, o1 = acc[mf][nf][1] + bb.y;
            float o2 = acc[mf][nf][2] + bb.x, o3 = acc[mf][nf][3] + bb.y;
            if (dst_sel < 0) {
                *(float2*)(Cext + (size_t)row * DIM + col)       = make_float2(o0, o1);
                *(float2*)(Cext + (size_t)(row + 8) * DIM + col) = make_float2(o2, o3);
            } else if (dst_sel == 2) {
                float h0 = __half2float(__float2half_rn(o0));
                float h1 = __half2float(__float2half_rn(o1));
                float h2 = __half2float(__float2half_rn(o2));
                float h3 = __half2float(__float2half_rn(o3));
                *(uint32_t*)(g_vh + (size_t)row * DIM + col)       = pack_f16(o0, o1);
                *(uint32_t*)(g_vh + (size_t)(row + 8) * DIM + col) = pack_f16(o2, o3);
                *(uint32_t*)(g_vl + (size_t)row * DIM + col)       = pack_f16(o0 - h0, o1 - h1);
                *(uint32_t*)(g_vl + (size_t)(row + 8) * DIM + col) = pack_f16(o2 - h2, o3 - h3);
            } else {
                __nv_bfloat16* dsth = (dst_sel == 0) ? g_qh : g_kh;
                __nv_bfloat16* dstl = (dst_sel == 0) ? g_ql : g_kl;
                float h0 = __bfloat162float(__float2bfloat16(o0));
                float h1 = __bfloat162float(__float2bfloat16(o1));
                float h2 = __bfloat162float(__float2bfloat16(o2));
                float h3 = __bfloat162float(__float2bfloat16(o3));
                *(uint32_t*)(dsth + (size_t)row * DIM + col)       = pack_bf16(h0, h1);
                *(uint32_t*)(dsth + (size_t)(row + 8) * DIM + col) = pack_bf16(h2, h3);
                *(uint32_t*)(dstl + (size_t)row * DIM + col)       = pack_bf16(o0 - h0, o1 - h1);
                *(uint32_t*)(dstl + (size_t)(row + 8) * DIM + col) = pack_bf16(o2 - h2, o3 - h3);
            }
        }
    }
}

// ---------------------------------------------------------------------------
// Flash attention: S = QK^T bf16x3 (QSCALE pre-folded, MUFU EX2 softmax);
// PV = Ph_fp16 * (Vh + Vl)_fp16. Interleaved mma issue order.
// ---------------------------------------------------------------------------
#define AKS 72
#define ATILE (64 * AKS * 2)              // 9216 B per array
#define ASTG  (4 * ATILE)                 // 36864 per stage
#define ASM_TOTAL (2 * ASTG)              // 73728

__global__ void __launch_bounds__(256, 2) attn_mma_kernel()
{
    extern __shared__ char smem[];
    const uint32_t sb = smem_u32(smem);
    const int tid  = threadIdx.x;
    const int wid  = tid >> 5;
    const int lane = tid & 31;
    const int g    = lane >> 2;
    const int q    = lane & 3;
    const int lj   = lane >> 3;
    const int li   = lane & 7;
    const int n    = blockIdx.y;
    const int qt   = blockIdx.x;

    const size_t nb = (size_t)n * 65536;
    const __nv_bfloat16* qhp = g_qh + nb + (qt * 128) * 64;
    const __nv_bfloat16* qlp = g_ql + nb + (qt * 128) * 64;

    uint32_t qah[4][4], qal[4][4];
    const int r0 = wid * 16 + g, r1 = r0 + 8;
#pragma unroll
    for (int ks = 0; ks < 4; ks++) {
        int c = ks * 16 + 2 * q;
        qah[ks][0] = *(const uint32_t*)(qhp + r0 * 64 + c);
        qah[ks][1] = *(const uint32_t*)(qhp + r1 * 64 + c);
        qah[ks][2] = *(const uint32_t*)(qhp + r0 * 64 + c + 8);
        qah[ks][3] = *(const uint32_t*)(qhp + r1 * 64 + c + 8);
        qal[ks][0] = *(const uint32_t*)(qlp + r0 * 64 + c);
        qal[ks][1] = *(const uint32_t*)(qlp + r1 * 64 + c);
        qal[ks][2] = *(const uint32_t*)(qlp + r0 * 64 + c + 8);
        qal[ks][3] = *(const uint32_t*)(qlp + r1 * 64 + c + 8);
    }

    float oacc[8][4];
#pragma unroll
    for (int i = 0; i < 8; i++)
#pragma unroll
        for (int j = 0; j < 4; j++) oacc[i][j] = 0.f;
    float m0 = -1e30f, m1 = -1e30f, l0 = 0.f, l1 = 0.f;

    auto stage = [&](int buf, int kt) {
        uint32_t base = sb + buf * ASTG;
#pragma unroll
        for (int it = 0; it < 2; it++) {
            int gdx = tid + 256 * it;
            int r  = gdx >> 3;
            int qq = gdx & 7;
            uint32_t doff = (uint32_t)(r * (AKS * 2) + qq * 16);
            size_t off = nb + (size_t)(kt * 64 + r) * 64 + qq * 8;
            cp16(base + doff,             g_kh + off);
            cp16(base + ATILE + doff,     g_kl + off);
            cp16(base + 2 * ATILE + doff, g_vh + off);
            cp16(base + 3 * ATILE + doff, g_vl + off);
        }
    };

    stage(0, 0);
    CP_COMMIT();

    const int b_row_lane = ((lj >> 1) << 3) + li;
    const int b_col_lane = (lj & 1) << 3;
    const int v_row_lane = ((lj & 1) << 3) + li;
    const int v_col_lane = (lj >> 1) << 3;

    for (int kt = 0; kt < 16; kt++) {
        if (kt < 15) {
            stage((kt + 1) & 1, kt + 1);
            CP_COMMIT();
            CP_WAIT(1);
        } else {
            CP_WAIT(0);
        }
        __syncthreads();

        const uint32_t base = sb + (kt & 1) * ASTG;
        const uint32_t bKh = base, bKl = base + ATILE;
        const uint32_t bVh = base + 2 * ATILE, bVl = base + 3 * ATILE;

        float s[8][4];
#pragma unroll
        for (int nf = 0; nf < 8; nf++)
#pragma unroll
            for (int j = 0; j < 4; j++) s[nf][j] = 0.f;

#pragma unroll
        for (int ks = 0; ks < 4; ks++) {
#pragma unroll
            for (int nfp = 0; nfp < 4; nfp++) {
                uint32_t ro = (uint32_t)((nfp * 16 + b_row_lane) * AKS
                                         + ks * 16 + b_col_lane) * 2;
                uint32_t h0, h1, h2, h3, l0r, l1r, l2r, l3r;
                LDSM_X4(h0, h1, h2, h3, bKh + ro);
                LDSM_X4(l0r, l1r, l2r, l3r, bKl + ro);
                // Interleaved: alternate the two accumulators per term
                MMA_BF16(s[2 * nfp],     qah[ks], h0, h1);
                MMA_BF16(s[2 * nfp + 1], qah[ks], h2, h3);
                MMA_BF16(s[2 * nfp],     qah[ks], l0r, l1r);
                MMA_BF16(s[2 * nfp + 1], qah[ks], l2r, l3r);
                MMA_BF16(s[2 * nfp],     qal[ks], h0, h1);
                MMA_BF16(s[2 * nfp + 1], qal[ks], h2, h3);
            }
        }

        float mn0 = m0, mn1 = m1;
#pragma unroll
        for (int nf = 0; nf < 8; nf++) {
            mn0 = fmaxf(mn0, fmaxf(s[nf][0], s[nf][1]));
            mn1 = fmaxf(mn1, fmaxf(s[nf][2], s[nf][3]));
        }
#pragma unroll
        for (int off = 1; off <= 2; off <<= 1) {
            mn0 = fmaxf(mn0, __shfl_xor_sync(0xffffffffu, mn0, off));
            mn1 = fmaxf(mn1, __shfl_xor_sync(0xffffffffu, mn1, off));
        }
        float f0 = ex2(m0 - mn0), f1 = ex2(m1 - mn1);
        m0 = mn0;  m1 = mn1;

        uint32_t ph[8], ph2[8];
        float ls0 = 0.f, ls1 = 0.f;
#pragma unroll
        for (int nf = 0; nf < 8; nf++) {
            float p0 = ex2(s[nf][0] - m0);
            float p1 = ex2(s[nf][1] - m0);
            float p2 = ex2(s[nf][2] - m1);
            float p3 = ex2(s[nf][3] - m1);
            ls0 += p0 + p1;  ls1 += p2 + p3;
            ph[nf]  = pack_f16(p0, p1);
            ph2[nf] = pack_f16(p2, p3);
        }
#pragma unroll
        for (int off = 1; off <= 2; off <<= 1) {
            ls0 += __shfl_xor_sync(0xffffffffu, ls0, off);
            ls1 += __shfl_xor_sync(0xffffffffu, ls1, off);
        }
        l0 = l0 * f0 + ls0;
        l1 = l1 * f1 + ls1;
#pragma unroll
        for (int dhf = 0; dhf < 8; dhf++) {
            oacc[dhf][0] *= f0;  oacc[dhf][1] *= f0;
            oacc[dhf][2] *= f1;  oacc[dhf][3] *= f1;
        }

        // O += Ph (Vh + Vl), fp16 mma, V via ldmatrix.trans, interleaved
#pragma unroll
        for (int ks = 0; ks < 4; ks++) {
            uint32_t a_h[4] = {ph[2 * ks], ph2[2 * ks], ph[2 * ks + 1], ph2[2 * ks + 1]};
#pragma unroll
            for (int dhp = 0; dhp < 4; dhp++) {
                uint32_t ro = (uint32_t)((ks * 16 + v_row_lane) * AKS
                                         + dhp * 16 + v_col_lane) * 2;
                uint32_t h0, h1, h2, h3, l0r, l1r, l2r, l3r;
                LDSM_X4_T(h0, h1, h2, h3, bVh + ro);
                LDSM_X4_T(l0r, l1r, l2r, l3r, bVl + ro);
                MMA_FP16(oacc[2 * dhp],     a_h, h0, h1);
                MMA_FP16(oacc[2 * dhp + 1], a_h, h2, h3);
                MMA_FP16(oacc[2 * dhp],     a_h, l0r, l1r);
                MMA_FP16(oacc[2 * dhp + 1], a_h, l2r, l3r);
            }
        }
        __syncthreads();
    }

    float inv0 = frcp(l0), inv1 = frcp(l1);
    const size_t ob0 = nb + (size_t)(qt * 128 + r0) * 64;
    const size_t ob1 = nb + (size_t)(qt * 128 + r1) * 64;
#pragma unroll
    for (int dhf = 0; dhf < 8; dhf++) {
        int col = dhf * 8 + 2 * q;
        float o0 = oacc[dhf][0] * inv0, o1 = oacc[dhf][1] * inv0;
        float o2 = oacc[dhf][2] * inv1, o3 = oacc[dhf][3] * inv1;
        float h0 = __bfloat162float(__float2bfloat16(o0));
        float h1 = __bfloat162float(__float2bfloat16(o1));
        float h2 = __bfloat162float(__float2bfloat16(o2));
        float h3 = __bfloat162float(__float2bfloat16(o3));
        *(uint32_t*)(g_ah + ob0 + col) = pack_bf16(h0, h1);
        *(uint32_t*)(g_ah + ob1 + col) = pack_bf16(h2, h3);
        *(uint32_t*)(g_al + ob0 + col) = pack_bf16(o0 - h0, o1 - h1);
        *(uint32_t*)(g_al + ob1 + col) = pack_bf16(o2 - h2, o3 - h3);
    }
}

// ---------------------------------------------------------------------------
extern "C" void kernel_launch(void* const* d_in, const int* in_sizes, int n_in,
                              void* d_out, int out_size)
{
    const float* x  = (const float*)d_in[0];
    const float* wq = (const float*)d_in[1];
    const float* bq = (const float*)d_in[2];
    const float* wk = (const float*)d_in[3];
    const float* bk = (const float*)d_in[4];
    const float* wv = (const float*)d_in[5];
    const float* bv = (const float*)d_in[6];
    const float* wo = (const float*)d_in[7];
    const float* bo = (const float*)d_in[8];
    float* out = (float*)d_out;

    static bool attr_set = false;
    if (!attr_set) {
        cudaFuncSetAttribute(gemm_mma_kernel,
                             cudaFuncAttributeMaxDynamicSharedMemorySize, GSM_TOTAL);
        cudaFuncSetAttribute(attn_mma_kernel,
                             cudaFuncAttributeMaxDynamicSharedMemorySize, ASM_TOTAL);
        attr_set = true;
    }

    prep_all_kernel<<<12288, 256>>>(wq, wk, wv, wo, x);

    // Fused Q/K/V projections: blockIdx.z selects weight + destination
    gemm_mma_kernel<<<dim3(4, 128, 3), 256, GSM_TOTAL>>>(bq, bk, bv, nullptr, 0);

    attn_mma_kernel<<<dim3(8, NBATCH), 256, ASM_TOTAL>>>();       // O -> g_ah/g_al

    // Output projection (wsel=3, fp32 out)
    gemm_mma_kernel<<<dim3(4, 128, 1), 256, GSM_TOTAL>>>(bo, nullptr, nullptr, out, -1);
}